// round 2
// baseline (speedup 1.0000x reference)
#include <cuda_runtime.h>
#include <cstdint>
#include <math.h>

#define NROWS 4096
#define DIM   2048
#define NK    4
#define EPSF  1e-6f

// ------------------------------------------------------------------
// Device scratch (no allocations allowed)
// ------------------------------------------------------------------
__device__ float g_h[(size_t)NROWS * DIM];   // h = s_b * (x W^T) + bias
__device__ float g_xn2[NROWS];               // |x_b|^2
__device__ float g_sp[NROWS];                // softplus(logit_b)
__device__ float g_c;                        // curvature c
__device__ float g_sc;                       // sqrt(c)
__device__ float g_an2[NK];                  // |a_k|^2
__device__ float g_w[NK];                    // softmax(anchor_weights)

// ------------------------------------------------------------------
// Helpers
// ------------------------------------------------------------------
__device__ __forceinline__ float blockReduceSum(float v, float* sbuf) {
    #pragma unroll
    for (int o = 16; o > 0; o >>= 1) v += __shfl_xor_sync(0xffffffffu, v, o);
    int w = threadIdx.x >> 5;
    if ((threadIdx.x & 31) == 0) sbuf[w] = v;
    __syncthreads();
    if (threadIdx.x < 32) {
        float t = (threadIdx.x < 8) ? sbuf[threadIdx.x] : 0.f;
        #pragma unroll
        for (int o = 4; o > 0; o >>= 1) t += __shfl_xor_sync(0xffffffffu, t, o);
        if (threadIdx.x == 0) sbuf[0] = t;
    }
    __syncthreads();
    float r = sbuf[0];
    __syncthreads();
    return r;
}

__device__ __forceinline__ float to_tf32(float x) {
    uint32_t u;
    asm("cvt.rna.tf32.f32 %0, %1;" : "=r"(u) : "f"(x));
    return __uint_as_float(u);
}

__device__ __forceinline__ float clip_artanh_arg(float z) {
    return fminf(fmaxf(z, -1.f + 1e-5f), 1.f - 1e-5f);
}

// ------------------------------------------------------------------
// Kernel 1: per-row |x|^2 and softplus(x . cw + cb)
// ------------------------------------------------------------------
__global__ __launch_bounds__(256) void k_rowstat(const float* __restrict__ x,
                                                 const float* __restrict__ cw,
                                                 const float* __restrict__ cb) {
    int row = blockIdx.x;
    const float4* xr = (const float4*)(x + (size_t)row * DIM);
    const float4* cr = (const float4*)cw;
    float dot = 0.f, nn = 0.f;
    #pragma unroll
    for (int i = 0; i < 2; i++) {
        int idx = threadIdx.x + i * 256;
        float4 a = xr[idx], b = cr[idx];
        dot += a.x * b.x + a.y * b.y + a.z * b.z + a.w * b.w;
        nn  += a.x * a.x + a.y * a.y + a.z * a.z + a.w * a.w;
    }
    __shared__ float sbuf[8];
    dot = blockReduceSum(dot, sbuf);
    nn  = blockReduceSum(nn, sbuf);
    if (threadIdx.x == 0) {
        g_xn2[row] = nn;
        float l = dot + cb[0];
        // stable softplus
        g_sp[row] = fmaxf(l, 0.f) + log1pf(expf(-fabsf(l)));
    }
}

// ------------------------------------------------------------------
// Kernel 2: c = mean(softplus), sqrt(c), |a_k|^2, softmax(anchor_weights)
// ------------------------------------------------------------------
__global__ __launch_bounds__(256) void k_scalars(const float* __restrict__ anchors,
                                                 const float* __restrict__ aw) {
    __shared__ float sbuf[8];
    float s = 0.f;
    for (int i = threadIdx.x; i < NROWS; i += 256) s += g_sp[i];
    s = blockReduceSum(s, sbuf);
    float c = s / (float)NROWS;

    for (int k = 0; k < NK; k++) {
        float v = 0.f;
        for (int j = threadIdx.x; j < DIM; j += 256) {
            float a = anchors[k * DIM + j];
            v += a * a;
        }
        v = blockReduceSum(v, sbuf);
        if (threadIdx.x == 0) g_an2[k] = v;
    }

    if (threadIdx.x == 0) {
        g_c = c;
        g_sc = sqrtf(c);
        float m = fmaxf(fmaxf(aw[0], aw[1]), fmaxf(aw[2], aw[3]));
        float e0 = expf(aw[0] - m), e1 = expf(aw[1] - m);
        float e2 = expf(aw[2] - m), e3 = expf(aw[3] - m);
        float inv = 1.f / (e0 + e1 + e2 + e3);
        g_w[0] = e0 * inv; g_w[1] = e1 * inv;
        g_w[2] = e2 * inv; g_w[3] = e3 * inv;
    }
}

// ------------------------------------------------------------------
// Kernel 3: TF32 GEMM  h = diag(s) * (X W^T) + bias
//   X: [4096, 2048] row-major;  W: [2048, 2048] row-major (N x K) -> row.col mma
//   Block tile 128x128, BK=32, 8 warps (4x2), warp tile 32x64, m16n8k8 tf32.
// ------------------------------------------------------------------
__device__ __forceinline__ float row_scale(int r, float sc) {
    float n = fmaxf(sqrtf(g_xn2[r]), EPSF);
    float z = sc * n;
    return atanhf(clip_artanh_arg(z)) / z;
}

__global__ __launch_bounds__(256) void k_gemm(const float* __restrict__ X,
                                              const float* __restrict__ W,
                                              const float* __restrict__ bias) {
    __shared__ float As[128][36];
    __shared__ float Bs[128][36];
    const int tid  = threadIdx.x;
    const int lane = tid & 31;
    const int warp = tid >> 5;
    const int bm = blockIdx.y * 128;
    const int bn = blockIdx.x * 128;
    const int wm = (warp >> 1) * 32;   // 4 warps along M
    const int wn = (warp & 1) * 64;    // 2 warps along N

    float acc[2][8][4];
    #pragma unroll
    for (int mi = 0; mi < 2; mi++)
        #pragma unroll
        for (int ni = 0; ni < 8; ni++)
            #pragma unroll
            for (int q = 0; q < 4; q++) acc[mi][ni][q] = 0.f;

    const int lr = tid >> 3;          // 0..31 (row within 32-row chunk)
    const int lc = (tid & 7) << 2;    // float4 col offset (0..28)
    const float* Xp = X + (size_t)(bm + lr) * DIM + lc;
    const float* Wp = W + (size_t)(bn + lr) * DIM + lc;

    const int g  = lane >> 2;
    const int tg = lane & 3;

    for (int k0 = 0; k0 < DIM; k0 += 32) {
        #pragma unroll
        for (int i = 0; i < 4; i++) {
            float4 v = *(const float4*)(Xp + (size_t)i * 32 * DIM + k0);
            v.x = to_tf32(v.x); v.y = to_tf32(v.y);
            v.z = to_tf32(v.z); v.w = to_tf32(v.w);
            *(float4*)(&As[lr + i * 32][lc]) = v;
            float4 u = *(const float4*)(Wp + (size_t)i * 32 * DIM + k0);
            u.x = to_tf32(u.x); u.y = to_tf32(u.y);
            u.z = to_tf32(u.z); u.w = to_tf32(u.w);
            *(float4*)(&Bs[lr + i * 32][lc]) = u;
        }
        __syncthreads();

        #pragma unroll
        for (int ks = 0; ks < 32; ks += 8) {
            uint32_t a[2][4];
            #pragma unroll
            for (int mi = 0; mi < 2; mi++) {
                int rb = wm + mi * 16 + g;
                a[mi][0] = __float_as_uint(As[rb][ks + tg]);
                a[mi][1] = __float_as_uint(As[rb + 8][ks + tg]);
                a[mi][2] = __float_as_uint(As[rb][ks + tg + 4]);
                a[mi][3] = __float_as_uint(As[rb + 8][ks + tg + 4]);
            }
            uint32_t b[8][2];
            #pragma unroll
            for (int ni = 0; ni < 8; ni++) {
                int nb = wn + ni * 8 + g;
                b[ni][0] = __float_as_uint(Bs[nb][ks + tg]);
                b[ni][1] = __float_as_uint(Bs[nb][ks + tg + 4]);
            }
            #pragma unroll
            for (int mi = 0; mi < 2; mi++)
                #pragma unroll
                for (int ni = 0; ni < 8; ni++) {
                    asm volatile(
                        "mma.sync.aligned.m16n8k8.row.col.f32.tf32.tf32.f32 "
                        "{%0,%1,%2,%3}, {%4,%5,%6,%7}, {%8,%9}, {%0,%1,%2,%3};\n"
                        : "+f"(acc[mi][ni][0]), "+f"(acc[mi][ni][1]),
                          "+f"(acc[mi][ni][2]), "+f"(acc[mi][ni][3])
                        : "r"(a[mi][0]), "r"(a[mi][1]), "r"(a[mi][2]), "r"(a[mi][3]),
                          "r"(b[ni][0]), "r"(b[ni][1]));
                }
        }
        __syncthreads();
    }

    // Epilogue: h = s_row * acc + bias
    float sc = g_sc;
    #pragma unroll
    for (int mi = 0; mi < 2; mi++) {
        int r0 = bm + wm + mi * 16 + g;
        float s0 = row_scale(r0, sc);
        float s1 = row_scale(r0 + 8, sc);
        #pragma unroll
        for (int ni = 0; ni < 8; ni++) {
            int cc = bn + wn + ni * 8 + tg * 2;
            float b0 = bias[cc], b1 = bias[cc + 1];
            float* o0 = g_h + (size_t)r0 * DIM + cc;
            o0[0] = fmaf(s0, acc[mi][ni][0], b0);
            o0[1] = fmaf(s0, acc[mi][ni][1], b1);
            float* o1 = g_h + (size_t)(r0 + 8) * DIM + cc;
            o1[0] = fmaf(s1, acc[mi][ni][2], b0);
            o1[1] = fmaf(s1, acc[mi][ni][3], b1);
        }
    }
}

// ------------------------------------------------------------------
// Kernel 4: per-row expmap0 + closed-form mobius anchor combine.
//   g_{b,k} = alpha_k * y + beta_k * a_k  (scalars from |y|^2,|a|^2,y.a)
//   out = (sum_k w_k alpha_k) * y + sum_k (w_k beta_k) a_k
// ------------------------------------------------------------------
__global__ __launch_bounds__(256) void k_final(const float* __restrict__ anchors,
                                               const float* __restrict__ tv,
                                               float* __restrict__ out) {
    int row = blockIdx.x;
    const float4* hr = (const float4*)(g_h + (size_t)row * DIM);
    float4 hv[2];
    float4 av[NK][2];
    float red[5] = {0.f, 0.f, 0.f, 0.f, 0.f};
    #pragma unroll
    for (int i = 0; i < 2; i++) {
        int idx = threadIdx.x + i * 256;
        float4 h = hr[idx];
        hv[i] = h;
        red[0] += h.x * h.x + h.y * h.y + h.z * h.z + h.w * h.w;
        #pragma unroll
        for (int k = 0; k < NK; k++) {
            float4 a = ((const float4*)(anchors + k * DIM))[idx];
            av[k][i] = a;
            red[1 + k] += h.x * a.x + h.y * a.y + h.z * a.z + h.w * a.w;
        }
    }
    __shared__ float sbuf[8];
    #pragma unroll
    for (int r = 0; r < 5; r++) red[r] = blockReduceSum(red[r], sbuf);

    float c = g_c, sc = g_sc;
    float h2 = red[0];
    float m = fmaxf(sqrtf(h2), EPSF);
    float scm = sc * m;
    float e = tanhf(scm) / scm;       // expmap0 scale: y = e * h
    float y2 = e * e * h2;

    float Acoef = 0.f;
    float Bk[NK];
    #pragma unroll
    for (int k = 0; k < NK; k++) {
        float ya  = e * red[1 + k];   // y . a_k
        float an2 = g_an2[k];
        // diff = mobius_add(-y, a) = (-P y + Q a)/D1
        float P  = 1.f - 2.f * c * ya + c * an2;
        float Q  = 1.f - c * y2;
        float D1 = fmaxf(1.f - 2.f * c * ya + c * c * y2 * an2, EPSF);
        float diff2 = (P * P * y2 - 2.f * P * Q * ya + Q * Q * an2) / (D1 * D1);
        float nd = fmaxf(sqrtf(fmaxf(diff2, 0.f)), EPSF);
        float z  = sc * nd;
        float ar = atanhf(clip_artanh_arg(z));
        float tau = tanhf(tv[k] * ar) / z;   // step = tau * diff
        float uy = -tau * P / D1;            // step = uy*y + ua*a
        float ua =  tau * Q / D1;
        float xys = uy * y2 + ua * ya;       // <y, step>
        float y2s = tau * tau * diff2;       // |step|^2
        float den2 = fmaxf(1.f + 2.f * c * xys + c * c * y2 * y2s, EPSF);
        float alpha = (1.f + 2.f * c * xys + c * y2s + (1.f - c * y2) * uy) / den2;
        float beta  = (1.f - c * y2) * ua / den2;
        float w = g_w[k];
        Acoef += w * alpha;
        Bk[k] = w * beta;
    }
    float Ae = Acoef * e;

    float4* outr = (float4*)(out + (size_t)row * DIM);
    #pragma unroll
    for (int i = 0; i < 2; i++) {
        float4 h = hv[i];
        float4 o;
        o.x = Ae * h.x; o.y = Ae * h.y; o.z = Ae * h.z; o.w = Ae * h.w;
        #pragma unroll
        for (int k = 0; k < NK; k++) {
            float4 a = av[k][i];
            float bk = Bk[k];
            o.x = fmaf(bk, a.x, o.x);
            o.y = fmaf(bk, a.y, o.y);
            o.z = fmaf(bk, a.z, o.z);
            o.w = fmaf(bk, a.w, o.w);
        }
        outr[threadIdx.x + i * 256] = o;
    }
}

// ------------------------------------------------------------------
// Launch
// ------------------------------------------------------------------
extern "C" void kernel_launch(void* const* d_in, const int* in_sizes, int n_in,
                              void* d_out, int out_size) {
    const float* x       = (const float*)d_in[0];
    const float* weight  = (const float*)d_in[1];
    const float* bias    = (const float*)d_in[2];
    const float* cw      = (const float*)d_in[3];
    const float* cb      = (const float*)d_in[4];
    const float* anchors = (const float*)d_in[5];
    const float* tv      = (const float*)d_in[6];
    const float* aw      = (const float*)d_in[7];
    float* out = (float*)d_out;

    k_rowstat<<<NROWS, 256>>>(x, cw, cb);
    k_scalars<<<1, 256>>>(anchors, aw);
    dim3 grid(DIM / 128, NROWS / 128);
    k_gemm<<<grid, 256>>>(x, weight, bias);
    k_final<<<NROWS, 256>>>(anchors, tv, out);
}

// round 4
// speedup vs baseline: 1.1601x; 1.1601x over previous
#include <cuda_runtime.h>
#include <cstdint>
#include <math.h>

#define NROWS 4096
#define DIM   2048
#define NK    4
#define EPSF  1e-6f

// GEMM tiling
#define MT 128
#define NT 128
#define KC 32
#define NSTAGE 3
#define NITER (DIM / KC)          // 64
#define ROWP 36                   // padded row (floats): 144B, 16B-aligned
#define A_STAGE_BYTES (MT * ROWP * 4)          // 18432
#define STAGE_BYTES   (2 * A_STAGE_BYTES)      // 36864 (A + B)
#define SMEM_TOTAL    (NSTAGE * STAGE_BYTES)   // 110592

// ------------------------------------------------------------------
// Device scratch (no allocations allowed)
// ------------------------------------------------------------------
__device__ float g_h[(size_t)NROWS * DIM];   // h = s_b*(xW^T)+bias
__device__ float g_xt[(size_t)NROWS * DIM];  // tf32-rounded X
__device__ float g_wt[(size_t)DIM * DIM];    // tf32-rounded W
__device__ float g_xn2[NROWS];
__device__ float g_sp[NROWS];
__device__ float g_c;
__device__ float g_sc;
__device__ float g_an2[NK];
__device__ float g_w[NK];

// ------------------------------------------------------------------
// Helpers
// ------------------------------------------------------------------
__device__ __forceinline__ uint32_t smem_u32(const void* p) {
    uint32_t a;
    asm("{ .reg .u64 t; cvta.to.shared.u64 t, %1; cvt.u32.u64 %0, t; }"
        : "=r"(a) : "l"(p));
    return a;
}

__device__ __forceinline__ float blockReduceSum(float v, float* sbuf) {
    #pragma unroll
    for (int o = 16; o > 0; o >>= 1) v += __shfl_xor_sync(0xffffffffu, v, o);
    int w = threadIdx.x >> 5;
    if ((threadIdx.x & 31) == 0) sbuf[w] = v;
    __syncthreads();
    if (threadIdx.x < 32) {
        float t = (threadIdx.x < 8) ? sbuf[threadIdx.x] : 0.f;
        #pragma unroll
        for (int o = 4; o > 0; o >>= 1) t += __shfl_xor_sync(0xffffffffu, t, o);
        if (threadIdx.x == 0) sbuf[0] = t;
    }
    __syncthreads();
    float r = sbuf[0];
    __syncthreads();
    return r;
}

__device__ __forceinline__ float to_tf32(float x) {
    uint32_t u;
    asm("cvt.rna.tf32.f32 %0, %1;" : "=r"(u) : "f"(x));
    return __uint_as_float(u);
}

__device__ __forceinline__ float clip_artanh_arg(float z) {
    return fminf(fmaxf(z, -1.f + 1e-5f), 1.f - 1e-5f);
}

// ------------------------------------------------------------------
// Kernel 1: per-row |x|^2, softplus(x.cw+cb), tf32-rounded X copy
// ------------------------------------------------------------------
__global__ __launch_bounds__(256) void k_rowstat(const float* __restrict__ x,
                                                 const float* __restrict__ cw,
                                                 const float* __restrict__ cb) {
    int row = blockIdx.x;
    const float4* xr = (const float4*)(x + (size_t)row * DIM);
    const float4* cr = (const float4*)cw;
    float4* xo = (float4*)(g_xt + (size_t)row * DIM);
    float dot = 0.f, nn = 0.f;
    #pragma unroll
    for (int i = 0; i < 2; i++) {
        int idx = threadIdx.x + i * 256;
        float4 a = xr[idx], b = cr[idx];
        dot += a.x * b.x + a.y * b.y + a.z * b.z + a.w * b.w;
        nn  += a.x * a.x + a.y * a.y + a.z * a.z + a.w * a.w;
        float4 t;
        t.x = to_tf32(a.x); t.y = to_tf32(a.y);
        t.z = to_tf32(a.z); t.w = to_tf32(a.w);
        xo[idx] = t;
    }
    __shared__ float sbuf[8];
    dot = blockReduceSum(dot, sbuf);
    nn  = blockReduceSum(nn, sbuf);
    if (threadIdx.x == 0) {
        g_xn2[row] = nn;
        float l = dot + cb[0];
        g_sp[row] = fmaxf(l, 0.f) + log1pf(expf(-fabsf(l)));
    }
}

// ------------------------------------------------------------------
// Kernel 1b: W -> tf32-rounded scratch
// ------------------------------------------------------------------
__global__ __launch_bounds__(256) void k_cvtW(const float* __restrict__ W) {
    int i = blockIdx.x * 256 + threadIdx.x;
    float4 v = ((const float4*)W)[i];
    float4 t;
    t.x = to_tf32(v.x); t.y = to_tf32(v.y);
    t.z = to_tf32(v.z); t.w = to_tf32(v.w);
    ((float4*)g_wt)[i] = t;
}

// ------------------------------------------------------------------
// Kernel 2: scalars
// ------------------------------------------------------------------
__global__ __launch_bounds__(256) void k_scalars(const float* __restrict__ anchors,
                                                 const float* __restrict__ aw) {
    __shared__ float sbuf[8];
    float s = 0.f;
    for (int i = threadIdx.x; i < NROWS; i += 256) s += g_sp[i];
    s = blockReduceSum(s, sbuf);
    float c = s / (float)NROWS;

    for (int k = 0; k < NK; k++) {
        float v = 0.f;
        for (int j = threadIdx.x; j < DIM; j += 256) {
            float a = anchors[k * DIM + j];
            v += a * a;
        }
        v = blockReduceSum(v, sbuf);
        if (threadIdx.x == 0) g_an2[k] = v;
    }

    if (threadIdx.x == 0) {
        g_c = c;
        g_sc = sqrtf(c);
        float m = fmaxf(fmaxf(aw[0], aw[1]), fmaxf(aw[2], aw[3]));
        float e0 = expf(aw[0] - m), e1 = expf(aw[1] - m);
        float e2 = expf(aw[2] - m), e3 = expf(aw[3] - m);
        float inv = 1.f / (e0 + e1 + e2 + e3);
        g_w[0] = e0 * inv; g_w[1] = e1 * inv;
        g_w[2] = e2 * inv; g_w[3] = e3 * inv;
    }
}

// ------------------------------------------------------------------
// Kernel 3: pipelined TF32 mma.sync GEMM  h = diag(s)*(X W^T) + bias
//   3-stage cp.async, 128x128 block, BK=32, 8 warps (4x2), warp 32x64.
// ------------------------------------------------------------------
__device__ __forceinline__ float row_scale(int r, float sc) {
    float n = fmaxf(sqrtf(g_xn2[r]), EPSF);
    float z = sc * n;
    return atanhf(clip_artanh_arg(z)) / z;
}

__device__ __forceinline__ void load_stage(uint32_t sb, int s, int k0,
                                           const float* Xp, const float* Wp,
                                           int lr, int lc) {
    uint32_t abase = sb + s * STAGE_BYTES;
    uint32_t bbase = abase + A_STAGE_BYTES;
    const float* xr = Xp + (size_t)lr * DIM + k0 + lc;
    const float* wr = Wp + (size_t)lr * DIM + k0 + lc;
    #pragma unroll
    for (int i = 0; i < 4; i++) {
        uint32_t off = ((lr + i * 32) * ROWP + lc) * 4;
        asm volatile("cp.async.cg.shared.global [%0], [%1], 16;"
                     :: "r"(abase + off), "l"(xr + (size_t)i * 32 * DIM));
        asm volatile("cp.async.cg.shared.global [%0], [%1], 16;"
                     :: "r"(bbase + off), "l"(wr + (size_t)i * 32 * DIM));
    }
}

__global__ void __launch_bounds__(256, 2) k_gemm(const float* __restrict__ bias) {
    extern __shared__ char smem[];
    uint32_t sb = smem_u32(smem);
    const int tid  = threadIdx.x;
    const int lane = tid & 31;
    const int warp = tid >> 5;
    const int bm = blockIdx.y * MT;
    const int bn = blockIdx.x * NT;
    const int wm = (warp >> 1) * 32;
    const int wn = (warp & 1) * 64;

    float acc[2][8][4];
    #pragma unroll
    for (int mi = 0; mi < 2; mi++)
        #pragma unroll
        for (int ni = 0; ni < 8; ni++)
            #pragma unroll
            for (int q = 0; q < 4; q++) acc[mi][ni][q] = 0.f;

    const int lr = tid >> 3;          // 0..31
    const int lc = (tid & 7) << 2;    // 0..28 (float4 col)
    const float* Xp = g_xt + (size_t)bm * DIM;
    const float* Wp = g_wt + (size_t)bn * DIM;

    const int g  = lane >> 2;
    const int tg = lane & 3;

    // prologue: stages 0 and 1
    load_stage(sb, 0, 0, Xp, Wp, lr, lc);
    asm volatile("cp.async.commit_group;" ::: "memory");
    load_stage(sb, 1, KC, Xp, Wp, lr, lc);
    asm volatile("cp.async.commit_group;" ::: "memory");

    for (int i = 0; i < NITER; i++) {
        asm volatile("cp.async.wait_group 1;" ::: "memory");
        __syncthreads();
        if (i + 2 < NITER)
            load_stage(sb, (i + 2) % NSTAGE, (i + 2) * KC, Xp, Wp, lr, lc);
        asm volatile("cp.async.commit_group;" ::: "memory");

        const float (*As)[ROWP] =
            (const float (*)[ROWP])(smem + (i % NSTAGE) * STAGE_BYTES);
        const float (*Bs)[ROWP] =
            (const float (*)[ROWP])(smem + (i % NSTAGE) * STAGE_BYTES + A_STAGE_BYTES);

        #pragma unroll
        for (int ks = 0; ks < KC; ks += 8) {
            uint32_t a[2][4];
            #pragma unroll
            for (int mi = 0; mi < 2; mi++) {
                int rb = wm + mi * 16 + g;
                a[mi][0] = __float_as_uint(As[rb][ks + tg]);
                a[mi][1] = __float_as_uint(As[rb + 8][ks + tg]);
                a[mi][2] = __float_as_uint(As[rb][ks + tg + 4]);
                a[mi][3] = __float_as_uint(As[rb + 8][ks + tg + 4]);
            }
            uint32_t b[8][2];
            #pragma unroll
            for (int ni = 0; ni < 8; ni++) {
                int nb = wn + ni * 8 + g;
                b[ni][0] = __float_as_uint(Bs[nb][ks + tg]);
                b[ni][1] = __float_as_uint(Bs[nb][ks + tg + 4]);
            }
            #pragma unroll
            for (int mi = 0; mi < 2; mi++)
                #pragma unroll
                for (int ni = 0; ni < 8; ni++) {
                    asm volatile(
                        "mma.sync.aligned.m16n8k8.row.col.f32.tf32.tf32.f32 "
                        "{%0,%1,%2,%3}, {%4,%5,%6,%7}, {%8,%9}, {%0,%1,%2,%3};\n"
                        : "+f"(acc[mi][ni][0]), "+f"(acc[mi][ni][1]),
                          "+f"(acc[mi][ni][2]), "+f"(acc[mi][ni][3])
                        : "r"(a[mi][0]), "r"(a[mi][1]), "r"(a[mi][2]), "r"(a[mi][3]),
                          "r"(b[ni][0]), "r"(b[ni][1]));
                }
        }
    }

    // Epilogue: h = s_row * acc + bias (registers only, no smem)
    float sc = g_sc;
    #pragma unroll
    for (int mi = 0; mi < 2; mi++) {
        int r0 = bm + wm + mi * 16 + g;
        float s0 = row_scale(r0, sc);
        float s1 = row_scale(r0 + 8, sc);
        #pragma unroll
        for (int ni = 0; ni < 8; ni++) {
            int cc = bn + wn + ni * 8 + tg * 2;
            float b0 = bias[cc], b1 = bias[cc + 1];
            float* o0 = g_h + (size_t)r0 * DIM + cc;
            o0[0] = fmaf(s0, acc[mi][ni][0], b0);
            o0[1] = fmaf(s0, acc[mi][ni][1], b1);
            float* o1 = g_h + (size_t)(r0 + 8) * DIM + cc;
            o1[0] = fmaf(s1, acc[mi][ni][2], b0);
            o1[1] = fmaf(s1, acc[mi][ni][3], b1);
        }
    }
}

// ------------------------------------------------------------------
// Kernel 4: per-row expmap0 + closed-form mobius anchor combine.
//   5 simultaneous reductions with 2 barriers total.
// ------------------------------------------------------------------
__global__ __launch_bounds__(256) void k_final(const float* __restrict__ anchors,
                                               const float* __restrict__ tv,
                                               float* __restrict__ out) {
    int row = blockIdx.x;
    const float4* hr = (const float4*)(g_h + (size_t)row * DIM);
    float4 hv[2];
    float4 av[NK][2];
    float red[5] = {0.f, 0.f, 0.f, 0.f, 0.f};
    #pragma unroll
    for (int i = 0; i < 2; i++) {
        int idx = threadIdx.x + i * 256;
        float4 h = hr[idx];
        hv[i] = h;
        red[0] += h.x * h.x + h.y * h.y + h.z * h.z + h.w * h.w;
        #pragma unroll
        for (int k = 0; k < NK; k++) {
            float4 a = ((const float4*)(anchors + k * DIM))[idx];
            av[k][i] = a;
            red[1 + k] += h.x * a.x + h.y * a.y + h.z * a.z + h.w * a.w;
        }
    }
    __shared__ float sbuf[8 * 5];
    __shared__ float sres[5];
    #pragma unroll
    for (int r = 0; r < 5; r++) {
        #pragma unroll
        for (int o = 16; o > 0; o >>= 1)
            red[r] += __shfl_xor_sync(0xffffffffu, red[r], o);
    }
    int w = threadIdx.x >> 5;
    if ((threadIdx.x & 31) == 0) {
        #pragma unroll
        for (int r = 0; r < 5; r++) sbuf[w * 5 + r] = red[r];
    }
    __syncthreads();
    if (threadIdx.x < 32) {
        #pragma unroll
        for (int r = 0; r < 5; r++) {
            float t = (threadIdx.x < 8) ? sbuf[threadIdx.x * 5 + r] : 0.f;
            #pragma unroll
            for (int o = 4; o > 0; o >>= 1) t += __shfl_xor_sync(0xffffffffu, t, o);
            if (threadIdx.x == 0) sres[r] = t;
        }
    }
    __syncthreads();

    float c = g_c, sc = g_sc;
    float h2 = sres[0];
    float m = fmaxf(sqrtf(h2), EPSF);
    float scm = sc * m;
    float e = tanhf(scm) / scm;
    float y2 = e * e * h2;

    float Acoef = 0.f;
    float Bk[NK];
    #pragma unroll
    for (int k = 0; k < NK; k++) {
        float ya  = e * sres[1 + k];
        float an2 = g_an2[k];
        float P  = 1.f - 2.f * c * ya + c * an2;
        float Q  = 1.f - c * y2;
        float D1 = fmaxf(1.f - 2.f * c * ya + c * c * y2 * an2, EPSF);
        float diff2 = (P * P * y2 - 2.f * P * Q * ya + Q * Q * an2) / (D1 * D1);
        float nd = fmaxf(sqrtf(fmaxf(diff2, 0.f)), EPSF);
        float z  = sc * nd;
        float ar = atanhf(clip_artanh_arg(z));
        float tau = tanhf(tv[k] * ar) / z;
        float uy = -tau * P / D1;
        float ua =  tau * Q / D1;
        float xys = uy * y2 + ua * ya;
        float y2s = tau * tau * diff2;
        float den2 = fmaxf(1.f + 2.f * c * xys + c * c * y2 * y2s, EPSF);
        float alpha = (1.f + 2.f * c * xys + c * y2s + (1.f - c * y2) * uy) / den2;
        float beta  = (1.f - c * y2) * ua / den2;
        float w2 = g_w[k];
        Acoef += w2 * alpha;
        Bk[k] = w2 * beta;
    }
    float Ae = Acoef * e;

    float4* outr = (float4*)(out + (size_t)row * DIM);
    #pragma unroll
    for (int i = 0; i < 2; i++) {
        float4 h = hv[i];
        float4 o;
        o.x = Ae * h.x; o.y = Ae * h.y; o.z = Ae * h.z; o.w = Ae * h.w;
        #pragma unroll
        for (int k = 0; k < NK; k++) {
            float4 a = av[k][i];
            float bk = Bk[k];
            o.x = fmaf(bk, a.x, o.x);
            o.y = fmaf(bk, a.y, o.y);
            o.z = fmaf(bk, a.z, o.z);
            o.w = fmaf(bk, a.w, o.w);
        }
        outr[threadIdx.x + i * 256] = o;
    }
}

// ------------------------------------------------------------------
// Launch
// ------------------------------------------------------------------
extern "C" void kernel_launch(void* const* d_in, const int* in_sizes, int n_in,
                              void* d_out, int out_size) {
    const float* x       = (const float*)d_in[0];
    const float* weight  = (const float*)d_in[1];
    const float* bias    = (const float*)d_in[2];
    const float* cw      = (const float*)d_in[3];
    const float* cb      = (const float*)d_in[4];
    const float* anchors = (const float*)d_in[5];
    const float* tv      = (const float*)d_in[6];
    const float* aw      = (const float*)d_in[7];
    float* out = (float*)d_out;

    cudaFuncSetAttribute(k_gemm, cudaFuncAttributeMaxDynamicSharedMemorySize,
                         SMEM_TOTAL);

    k_rowstat<<<NROWS, 256>>>(x, cw, cb);
    k_cvtW<<<DIM * DIM / 4 / 256, 256>>>(weight);
    k_scalars<<<1, 256>>>(anchors, aw);
    dim3 grid(DIM / NT, NROWS / MT);
    k_gemm<<<grid, 256, SMEM_TOTAL>>>(bias);
    k_final<<<NROWS, 256>>>(anchors, tv, out);
}

// round 5
// speedup vs baseline: 1.6701x; 1.4396x over previous
#include <cuda_runtime.h>
#include <cuda_fp16.h>
#include <cstdint>
#include <math.h>

#define NROWS 4096
#define DIM   2048
#define NK    4
#define EPSF  1e-6f

// GEMM tiling (fp16, mma.m16n8k16)
#define MT 128
#define NT 128
#define KC 32                     // K elements (halves) per stage
#define NSTAGE 4
#define NITER (DIM / KC)          // 64
#define ROWB 80                   // smem bytes per row: 64 data + 16 pad
#define A_STAGE_BYTES (MT * ROWB)              // 10240
#define STAGE_BYTES   (2 * A_STAGE_BYTES)      // 20480
#define SMEM_TOTAL    (NSTAGE * STAGE_BYTES)   // 81920

#define SCALE     32.0f
#define SCALE_INV 9.765625e-4f    // 1/1024

// ------------------------------------------------------------------
// Device scratch
// ------------------------------------------------------------------
__device__ float  g_h[(size_t)NROWS * DIM];
__device__ __half g_xh[(size_t)NROWS * DIM];
__device__ __half g_wh[(size_t)DIM * DIM];
__device__ float  g_part[(size_t)NROWS * 32 * 5];   // per-row partial sums
__device__ float  g_Ae[NROWS];
__device__ float  g_Bco[NROWS * NK];
__device__ float  g_xn2[NROWS];
__device__ float  g_sp[NROWS];
__device__ float  g_c;
__device__ float  g_sc;
__device__ float  g_an2[NK];
__device__ float  g_w[NK];

// ------------------------------------------------------------------
// Helpers
// ------------------------------------------------------------------
__device__ __forceinline__ uint32_t smem_u32(const void* p) {
    uint32_t a;
    asm("{ .reg .u64 t; cvta.to.shared.u64 t, %1; cvt.u32.u64 %0, t; }"
        : "=r"(a) : "l"(p));
    return a;
}

__device__ __forceinline__ float blockReduceSum(float v, float* sbuf) {
    #pragma unroll
    for (int o = 16; o > 0; o >>= 1) v += __shfl_xor_sync(0xffffffffu, v, o);
    int w = threadIdx.x >> 5;
    if ((threadIdx.x & 31) == 0) sbuf[w] = v;
    __syncthreads();
    if (threadIdx.x < 32) {
        float t = (threadIdx.x < 8) ? sbuf[threadIdx.x] : 0.f;
        #pragma unroll
        for (int o = 4; o > 0; o >>= 1) t += __shfl_xor_sync(0xffffffffu, t, o);
        if (threadIdx.x == 0) sbuf[0] = t;
    }
    __syncthreads();
    float r = sbuf[0];
    __syncthreads();
    return r;
}

__device__ __forceinline__ float clip_artanh_arg(float z) {
    return fminf(fmaxf(z, -1.f + 1e-5f), 1.f - 1e-5f);
}

__device__ __forceinline__ void ldsm4(uint32_t addr, uint32_t& r0, uint32_t& r1,
                                      uint32_t& r2, uint32_t& r3) {
    asm volatile("ldmatrix.sync.aligned.m8n8.x4.shared.b16 {%0,%1,%2,%3}, [%4];"
                 : "=r"(r0), "=r"(r1), "=r"(r2), "=r"(r3) : "r"(addr));
}

// ------------------------------------------------------------------
// Kernel 1: per-row |x|^2, softplus(x.cw+cb), fp16 (x*32) copy
// ------------------------------------------------------------------
__global__ __launch_bounds__(256) void k_rowstat(const float* __restrict__ x,
                                                 const float* __restrict__ cw,
                                                 const float* __restrict__ cb) {
    int row = blockIdx.x;
    const float4* xr = (const float4*)(x + (size_t)row * DIM);
    const float4* cr = (const float4*)cw;
    __half2* xo = (__half2*)(g_xh + (size_t)row * DIM);
    float dot = 0.f, nn = 0.f;
    #pragma unroll
    for (int i = 0; i < 2; i++) {
        int idx = threadIdx.x + i * 256;
        float4 a = xr[idx], b = cr[idx];
        dot += a.x * b.x + a.y * b.y + a.z * b.z + a.w * b.w;
        nn  += a.x * a.x + a.y * a.y + a.z * a.z + a.w * a.w;
        xo[idx * 2]     = __floats2half2_rn(a.x * SCALE, a.y * SCALE);
        xo[idx * 2 + 1] = __floats2half2_rn(a.z * SCALE, a.w * SCALE);
    }
    __shared__ float sbuf[8];
    dot = blockReduceSum(dot, sbuf);
    nn  = blockReduceSum(nn, sbuf);
    if (threadIdx.x == 0) {
        g_xn2[row] = nn;
        float l = dot + cb[0];
        g_sp[row] = fmaxf(l, 0.f) + log1pf(expf(-fabsf(l)));
    }
}

// ------------------------------------------------------------------
// Kernel 1b: W -> fp16 (w*32)
// ------------------------------------------------------------------
__global__ __launch_bounds__(256) void k_cvtW(const float* __restrict__ W) {
    int i = blockIdx.x * 256 + threadIdx.x;
    float4 v = ((const float4*)W)[i];
    __half2* o = (__half2*)g_wh;
    o[i * 2]     = __floats2half2_rn(v.x * SCALE, v.y * SCALE);
    o[i * 2 + 1] = __floats2half2_rn(v.z * SCALE, v.w * SCALE);
}

// ------------------------------------------------------------------
// Kernel 2: scalars
// ------------------------------------------------------------------
__global__ __launch_bounds__(256) void k_scalars(const float* __restrict__ anchors,
                                                 const float* __restrict__ aw) {
    __shared__ float sbuf[8];
    float s = 0.f;
    for (int i = threadIdx.x; i < NROWS; i += 256) s += g_sp[i];
    s = blockReduceSum(s, sbuf);
    float c = s / (float)NROWS;

    for (int k = 0; k < NK; k++) {
        float v = 0.f;
        for (int j = threadIdx.x; j < DIM; j += 256) {
            float a = anchors[k * DIM + j];
            v += a * a;
        }
        v = blockReduceSum(v, sbuf);
        if (threadIdx.x == 0) g_an2[k] = v;
    }

    if (threadIdx.x == 0) {
        g_c = c;
        g_sc = sqrtf(c);
        float m = fmaxf(fmaxf(aw[0], aw[1]), fmaxf(aw[2], aw[3]));
        float e0 = expf(aw[0] - m), e1 = expf(aw[1] - m);
        float e2 = expf(aw[2] - m), e3 = expf(aw[3] - m);
        float inv = 1.f / (e0 + e1 + e2 + e3);
        g_w[0] = e0 * inv; g_w[1] = e1 * inv;
        g_w[2] = e2 * inv; g_w[3] = e3 * inv;
    }
}

// ------------------------------------------------------------------
// Kernel 3: fp16 mma.sync GEMM + fused epilogue partial reductions
// ------------------------------------------------------------------
__device__ __forceinline__ float row_scale(int r, float sc) {
    float n = fmaxf(sqrtf(g_xn2[r]), EPSF);
    float z = sc * n;
    return atanhf(clip_artanh_arg(z)) / z;
}

__device__ __forceinline__ void load_stage(uint32_t sb, int s, int chunk,
                                           const __half* Xp, const __half* Wp,
                                           int tid) {
    uint32_t abase = sb + s * STAGE_BYTES;
    uint32_t bbase = abase + A_STAGE_BYTES;
    int row = tid >> 1;
    int hof = (tid & 1) * 16;           // halves offset within row
    uint32_t soff = row * ROWB + (tid & 1) * 32;
    const __half* xr = Xp + (size_t)row * DIM + chunk * KC + hof;
    const __half* wr = Wp + (size_t)row * DIM + chunk * KC + hof;
    #pragma unroll
    for (int i = 0; i < 2; i++) {
        asm volatile("cp.async.cg.shared.global [%0], [%1], 16;"
                     :: "r"(abase + soff + i * 16), "l"(xr + i * 8));
        asm volatile("cp.async.cg.shared.global [%0], [%1], 16;"
                     :: "r"(bbase + soff + i * 16), "l"(wr + i * 8));
    }
}

__global__ void __launch_bounds__(256, 2) k_gemm(const float* __restrict__ bias,
                                                 const float* __restrict__ anchors) {
    extern __shared__ char smem[];
    uint32_t sb = smem_u32(smem);
    const int tid  = threadIdx.x;
    const int lane = tid & 31;
    const int warp = tid >> 5;
    const int bm = blockIdx.y * MT;
    const int bn = blockIdx.x * NT;
    const int wm = (warp >> 1) * 32;
    const int wn = (warp & 1) * 64;

    float acc[2][8][4];
    #pragma unroll
    for (int mi = 0; mi < 2; mi++)
        #pragma unroll
        for (int ni = 0; ni < 8; ni++)
            #pragma unroll
            for (int q = 0; q < 4; q++) acc[mi][ni][q] = 0.f;

    const __half* Xp = g_xh + (size_t)bm * DIM;
    const __half* Wp = g_wh + (size_t)bn * DIM;

    const int g  = lane >> 2;
    const int tg = lane & 3;

    // ldmatrix per-lane address components
    const uint32_t a_row = wm + (lane & 15);
    const uint32_t a_koff = (lane >> 4) * 16;
    const uint32_t b_row = wn + ((lane >> 4) << 3) + (lane & 7);
    const uint32_t b_koff = ((lane >> 3) & 1) * 16;

    load_stage(sb, 0, 0, Xp, Wp, tid);
    asm volatile("cp.async.commit_group;" ::: "memory");
    load_stage(sb, 1, 1, Xp, Wp, tid);
    asm volatile("cp.async.commit_group;" ::: "memory");
    load_stage(sb, 2, 2, Xp, Wp, tid);
    asm volatile("cp.async.commit_group;" ::: "memory");

    for (int i = 0; i < NITER; i++) {
        asm volatile("cp.async.wait_group 2;" ::: "memory");
        __syncthreads();
        if (i + 3 < NITER)
            load_stage(sb, (i + 3) & 3, i + 3, Xp, Wp, tid);
        asm volatile("cp.async.commit_group;" ::: "memory");

        uint32_t abase = sb + (i & 3) * STAGE_BYTES;
        uint32_t bbase = abase + A_STAGE_BYTES;

        #pragma unroll
        for (int ks = 0; ks < 2; ks++) {
            uint32_t a[2][4];
            #pragma unroll
            for (int mi = 0; mi < 2; mi++)
                ldsm4(abase + (a_row + mi * 16) * ROWB + ks * 32 + a_koff,
                      a[mi][0], a[mi][1], a[mi][2], a[mi][3]);
            uint32_t b[8][2];
            #pragma unroll
            for (int p = 0; p < 4; p++)
                ldsm4(bbase + (b_row + p * 16) * ROWB + ks * 32 + b_koff,
                      b[2 * p][0], b[2 * p][1], b[2 * p + 1][0], b[2 * p + 1][1]);
            #pragma unroll
            for (int mi = 0; mi < 2; mi++)
                #pragma unroll
                for (int ni = 0; ni < 8; ni++) {
                    asm volatile(
                        "mma.sync.aligned.m16n8k16.row.col.f32.f16.f16.f32 "
                        "{%0,%1,%2,%3}, {%4,%5,%6,%7}, {%8,%9}, {%0,%1,%2,%3};\n"
                        : "+f"(acc[mi][ni][0]), "+f"(acc[mi][ni][1]),
                          "+f"(acc[mi][ni][2]), "+f"(acc[mi][ni][3])
                        : "r"(a[mi][0]), "r"(a[mi][1]), "r"(a[mi][2]), "r"(a[mi][3]),
                          "r"(b[ni][0]), "r"(b[ni][1]));
                }
        }
    }

    // Epilogue: h = s_row * acc/1024 + bias; store + per-row partial sums
    float sc = g_sc;
    #pragma unroll
    for (int mi = 0; mi < 2; mi++) {
        int r0 = bm + wm + mi * 16 + g;
        float s0 = row_scale(r0, sc) * SCALE_INV;
        float s1 = row_scale(r0 + 8, sc) * SCALE_INV;
        float p0[5] = {0.f, 0.f, 0.f, 0.f, 0.f};
        float p1[5] = {0.f, 0.f, 0.f, 0.f, 0.f};
        #pragma unroll
        for (int ni = 0; ni < 8; ni++) {
            int cc = bn + wn + ni * 8 + tg * 2;
            float b0 = bias[cc], b1 = bias[cc + 1];
            float h00 = fmaf(s0, acc[mi][ni][0], b0);
            float h01 = fmaf(s0, acc[mi][ni][1], b1);
            float h10 = fmaf(s1, acc[mi][ni][2], b0);
            float h11 = fmaf(s1, acc[mi][ni][3], b1);
            float* o0 = g_h + (size_t)r0 * DIM + cc;
            o0[0] = h00; o0[1] = h01;
            float* o1 = g_h + (size_t)(r0 + 8) * DIM + cc;
            o1[0] = h10; o1[1] = h11;
            p0[0] += h00 * h00 + h01 * h01;
            p1[0] += h10 * h10 + h11 * h11;
            #pragma unroll
            for (int k = 0; k < NK; k++) {
                float a0 = anchors[k * DIM + cc];
                float a1 = anchors[k * DIM + cc + 1];
                p0[1 + k] += h00 * a0 + h01 * a1;
                p1[1 + k] += h10 * a0 + h11 * a1;
            }
        }
        #pragma unroll
        for (int q = 0; q < 5; q++) {
            p0[q] += __shfl_xor_sync(0xffffffffu, p0[q], 1);
            p0[q] += __shfl_xor_sync(0xffffffffu, p0[q], 2);
            p1[q] += __shfl_xor_sync(0xffffffffu, p1[q], 1);
            p1[q] += __shfl_xor_sync(0xffffffffu, p1[q], 2);
        }
        if (tg == 0) {
            int pi = blockIdx.x * 2 + (warp & 1);
            float* d0 = g_part + ((size_t)r0 * 32 + pi) * 5;
            float* d1 = g_part + ((size_t)(r0 + 8) * 32 + pi) * 5;
            #pragma unroll
            for (int q = 0; q < 5; q++) { d0[q] = p0[q]; d1[q] = p1[q]; }
        }
    }
}

// ------------------------------------------------------------------
// Kernel 3b: per-row coefficients from partial sums
// ------------------------------------------------------------------
__global__ __launch_bounds__(256) void k_coef(const float* __restrict__ tv) {
    int row = blockIdx.x * 256 + threadIdx.x;
    const float* pp = g_part + (size_t)row * 160;
    float red[5] = {0.f, 0.f, 0.f, 0.f, 0.f};
    for (int p = 0; p < 32; p++)
        #pragma unroll
        for (int q = 0; q < 5; q++) red[q] += pp[p * 5 + q];

    float c = g_c, sc = g_sc;
    float h2 = red[0];
    float m = fmaxf(sqrtf(h2), EPSF);
    float scm = sc * m;
    float e = tanhf(scm) / scm;
    float y2 = e * e * h2;

    float Acoef = 0.f;
    #pragma unroll
    for (int k = 0; k < NK; k++) {
        float ya  = e * red[1 + k];
        float an2 = g_an2[k];
        float P  = 1.f - 2.f * c * ya + c * an2;
        float Q  = 1.f - c * y2;
        float D1 = fmaxf(1.f - 2.f * c * ya + c * c * y2 * an2, EPSF);
        float diff2 = (P * P * y2 - 2.f * P * Q * ya + Q * Q * an2) / (D1 * D1);
        float nd = fmaxf(sqrtf(fmaxf(diff2, 0.f)), EPSF);
        float z  = sc * nd;
        float ar = atanhf(clip_artanh_arg(z));
        float tau = tanhf(tv[k] * ar) / z;
        float uy = -tau * P / D1;
        float ua =  tau * Q / D1;
        float xys = uy * y2 + ua * ya;
        float y2s = tau * tau * diff2;
        float den2 = fmaxf(1.f + 2.f * c * xys + c * c * y2 * y2s, EPSF);
        float alpha = (1.f + 2.f * c * xys + c * y2s + (1.f - c * y2) * uy) / den2;
        float beta  = (1.f - c * y2) * ua / den2;
        float w2 = g_w[k];
        Acoef += w2 * alpha;
        g_Bco[row * NK + k] = w2 * beta;
    }
    g_Ae[row] = Acoef * e;
}

// ------------------------------------------------------------------
// Kernel 4: pure streaming combine  out = Ae*h + sum_k Bk*a_k
// ------------------------------------------------------------------
__global__ __launch_bounds__(256) void k_final(const float* __restrict__ anchors,
                                               float* __restrict__ out) {
    int row = blockIdx.x;
    float Ae = g_Ae[row];
    float B0 = g_Bco[row * NK + 0];
    float B1 = g_Bco[row * NK + 1];
    float B2 = g_Bco[row * NK + 2];
    float B3 = g_Bco[row * NK + 3];
    const float4* hr = (const float4*)(g_h + (size_t)row * DIM);
    const float4* a0 = (const float4*)(anchors);
    const float4* a1 = (const float4*)(anchors + DIM);
    const float4* a2 = (const float4*)(anchors + 2 * DIM);
    const float4* a3 = (const float4*)(anchors + 3 * DIM);
    float4* outr = (float4*)(out + (size_t)row * DIM);
    #pragma unroll
    for (int i = 0; i < 2; i++) {
        int idx = threadIdx.x + i * 256;
        float4 h = hr[idx];
        float4 v0 = a0[idx], v1 = a1[idx], v2 = a2[idx], v3 = a3[idx];
        float4 o;
        o.x = Ae * h.x; o.y = Ae * h.y; o.z = Ae * h.z; o.w = Ae * h.w;
        o.x = fmaf(B0, v0.x, o.x); o.y = fmaf(B0, v0.y, o.y);
        o.z = fmaf(B0, v0.z, o.z); o.w = fmaf(B0, v0.w, o.w);
        o.x = fmaf(B1, v1.x, o.x); o.y = fmaf(B1, v1.y, o.y);
        o.z = fmaf(B1, v1.z, o.z); o.w = fmaf(B1, v1.w, o.w);
        o.x = fmaf(B2, v2.x, o.x); o.y = fmaf(B2, v2.y, o.y);
        o.z = fmaf(B2, v2.z, o.z); o.w = fmaf(B2, v2.w, o.w);
        o.x = fmaf(B3, v3.x, o.x); o.y = fmaf(B3, v3.y, o.y);
        o.z = fmaf(B3, v3.z, o.z); o.w = fmaf(B3, v3.w, o.w);
        outr[idx] = o;
    }
}

// ------------------------------------------------------------------
// Launch
// ------------------------------------------------------------------
extern "C" void kernel_launch(void* const* d_in, const int* in_sizes, int n_in,
                              void* d_out, int out_size) {
    const float* x       = (const float*)d_in[0];
    const float* weight  = (const float*)d_in[1];
    const float* bias    = (const float*)d_in[2];
    const float* cw      = (const float*)d_in[3];
    const float* cb      = (const float*)d_in[4];
    const float* anchors = (const float*)d_in[5];
    const float* tv      = (const float*)d_in[6];
    const float* aw      = (const float*)d_in[7];
    float* out = (float*)d_out;

    cudaFuncSetAttribute(k_gemm, cudaFuncAttributeMaxDynamicSharedMemorySize,
                         SMEM_TOTAL);

    k_rowstat<<<NROWS, 256>>>(x, cw, cb);
    k_cvtW<<<DIM * DIM / 4 / 256, 256>>>(weight);
    k_scalars<<<1, 256>>>(anchors, aw);
    dim3 grid(DIM / NT, NROWS / MT);
    k_gemm<<<grid, 256, SMEM_TOTAL>>>(bias, anchors);
    k_coef<<<NROWS / 256, 256>>>(tv);
    k_final<<<NROWS, 256>>>(anchors, out);
}

// round 7
// speedup vs baseline: 1.6715x; 1.0009x over previous
#include <cuda_runtime.h>
#include <cuda_fp16.h>
#include <cstdint>
#include <math.h>

#define NROWS 4096
#define DIM   2048
#define NK    4
#define EPSF  1e-6f

// GEMM tiling (fp16, mma.m16n8k16), block 128x256, warp 64x64, 8 warps
#define MT 128
#define NT 256
#define KC 32                     // K halves per stage
#define NSTAGE 4
#define NITER (DIM / KC)          // 64
#define ROWB 80                   // smem bytes per row: 64 data + 16 pad
#define A_STAGE_BYTES (MT * ROWB)              // 10240
#define B_STAGE_BYTES (NT * ROWB)              // 20480
#define STAGE_BYTES   (A_STAGE_BYTES + B_STAGE_BYTES)   // 30720
#define SMEM_TOTAL    (NSTAGE * STAGE_BYTES)   // 122880

#define SCALE     32.0f
#define SCALE_INV 9.765625e-4f    // 1/1024

// ------------------------------------------------------------------
// Device scratch
// ------------------------------------------------------------------
__device__ float  g_h[(size_t)NROWS * DIM];
__device__ __half g_xh[(size_t)NROWS * DIM];
__device__ __half g_wh[(size_t)DIM * DIM];
__device__ float  g_part[(size_t)NROWS * 32 * 5];
__device__ float  g_Ae[NROWS];
__device__ float  g_Bco[NROWS * NK];
__device__ float  g_xn2[NROWS];
__device__ float  g_sp[NROWS];
__device__ float  g_c;
__device__ float  g_sc;
__device__ float  g_an2[NK];
__device__ float  g_w[NK];

// ------------------------------------------------------------------
// Helpers
// ------------------------------------------------------------------
__device__ __forceinline__ uint32_t smem_u32(const void* p) {
    uint32_t a;
    asm("{ .reg .u64 t; cvta.to.shared.u64 t, %1; cvt.u32.u64 %0, t; }"
        : "=r"(a) : "l"(p));
    return a;
}

__device__ __forceinline__ float blockReduceSum(float v, float* sbuf) {
    #pragma unroll
    for (int o = 16; o > 0; o >>= 1) v += __shfl_xor_sync(0xffffffffu, v, o);
    int w = threadIdx.x >> 5;
    if ((threadIdx.x & 31) == 0) sbuf[w] = v;
    __syncthreads();
    if (threadIdx.x < 32) {
        float t = (threadIdx.x < 8) ? sbuf[threadIdx.x] : 0.f;
        #pragma unroll
        for (int o = 4; o > 0; o >>= 1) t += __shfl_xor_sync(0xffffffffu, t, o);
        if (threadIdx.x == 0) sbuf[0] = t;
    }
    __syncthreads();
    float r = sbuf[0];
    __syncthreads();
    return r;
}

__device__ __forceinline__ float clip_artanh_arg(float z) {
    return fminf(fmaxf(z, -1.f + 1e-5f), 1.f - 1e-5f);
}

__device__ __forceinline__ void ldsm4(uint32_t addr, uint32_t& r0, uint32_t& r1,
                                      uint32_t& r2, uint32_t& r3) {
    asm volatile("ldmatrix.sync.aligned.m8n8.x4.shared.b16 {%0,%1,%2,%3}, [%4];"
                 : "=r"(r0), "=r"(r1), "=r"(r2), "=r"(r3) : "r"(addr));
}

// ------------------------------------------------------------------
// Kernel 1: per-row |x|^2, softplus(x.cw+cb), fp16 (x*32) copy
// ------------------------------------------------------------------
__global__ __launch_bounds__(256) void k_rowstat(const float* __restrict__ x,
                                                 const float* __restrict__ cw,
                                                 const float* __restrict__ cb) {
    int row = blockIdx.x;
    const float4* xr = (const float4*)(x + (size_t)row * DIM);
    const float4* cr = (const float4*)cw;
    __half2* xo = (__half2*)(g_xh + (size_t)row * DIM);
    float dot = 0.f, nn = 0.f;
    #pragma unroll
    for (int i = 0; i < 2; i++) {
        int idx = threadIdx.x + i * 256;
        float4 a = xr[idx], b = cr[idx];
        dot += a.x * b.x + a.y * b.y + a.z * b.z + a.w * b.w;
        nn  += a.x * a.x + a.y * a.y + a.z * a.z + a.w * a.w;
        xo[idx * 2]     = __floats2half2_rn(a.x * SCALE, a.y * SCALE);
        xo[idx * 2 + 1] = __floats2half2_rn(a.z * SCALE, a.w * SCALE);
    }
    __shared__ float sbuf[8];
    dot = blockReduceSum(dot, sbuf);
    nn  = blockReduceSum(nn, sbuf);
    if (threadIdx.x == 0) {
        g_xn2[row] = nn;
        float l = dot + cb[0];
        g_sp[row] = fmaxf(l, 0.f) + log1pf(expf(-fabsf(l)));
    }
}

// ------------------------------------------------------------------
// Kernel 1b: W -> fp16 (w*32)
// ------------------------------------------------------------------
__global__ __launch_bounds__(256) void k_cvtW(const float* __restrict__ W) {
    int i = blockIdx.x * 256 + threadIdx.x;
    float4 v = ((const float4*)W)[i];
    __half2* o = (__half2*)g_wh;
    o[i * 2]     = __floats2half2_rn(v.x * SCALE, v.y * SCALE);
    o[i * 2 + 1] = __floats2half2_rn(v.z * SCALE, v.w * SCALE);
}

// ------------------------------------------------------------------
// Kernel 2: scalars
// ------------------------------------------------------------------
__global__ __launch_bounds__(256) void k_scalars(const float* __restrict__ anchors,
                                                 const float* __restrict__ aw) {
    __shared__ float sbuf[8];
    float s = 0.f;
    for (int i = threadIdx.x; i < NROWS; i += 256) s += g_sp[i];
    s = blockReduceSum(s, sbuf);
    float c = s / (float)NROWS;

    for (int k = 0; k < NK; k++) {
        float v = 0.f;
        for (int j = threadIdx.x; j < DIM; j += 256) {
            float a = anchors[k * DIM + j];
            v += a * a;
        }
        v = blockReduceSum(v, sbuf);
        if (threadIdx.x == 0) g_an2[k] = v;
    }

    if (threadIdx.x == 0) {
        g_c = c;
        g_sc = sqrtf(c);
        float m = fmaxf(fmaxf(aw[0], aw[1]), fmaxf(aw[2], aw[3]));
        float e0 = expf(aw[0] - m), e1 = expf(aw[1] - m);
        float e2 = expf(aw[2] - m), e3 = expf(aw[3] - m);
        float inv = 1.f / (e0 + e1 + e2 + e3);
        g_w[0] = e0 * inv; g_w[1] = e1 * inv;
        g_w[2] = e2 * inv; g_w[3] = e3 * inv;
    }
}

// ------------------------------------------------------------------
// Kernel 3: fp16 mma.sync GEMM (128x256 block, 64x64 warps) + fused partials
// ------------------------------------------------------------------
__device__ __forceinline__ float row_scale(int r, float sc) {
    float n = fmaxf(sqrtf(g_xn2[r]), EPSF);
    float z = sc * n;
    return atanhf(clip_artanh_arg(z)) / z;
}

__device__ __forceinline__ void load_stage(uint32_t sb, int s, int chunk,
                                           const __half* Xp, const __half* Wp,
                                           int tid) {
    uint32_t abase = sb + s * STAGE_BYTES;
    uint32_t bbase = abase + A_STAGE_BYTES;
    #pragma unroll
    for (int i = 0; i < 6; i++) {
        int idx  = i * 256 + tid;      // 0..1535
        int row  = idx >> 2;           // 0..383
        int quad = idx & 3;
        if (row < MT) {
            const __half* src = Xp + (size_t)row * DIM + chunk * KC + quad * 8;
            asm volatile("cp.async.cg.shared.global [%0], [%1], 16;"
                         :: "r"(abase + row * ROWB + quad * 16), "l"(src));
        } else {
            int br = row - MT;
            const __half* src = Wp + (size_t)br * DIM + chunk * KC + quad * 8;
            asm volatile("cp.async.cg.shared.global [%0], [%1], 16;"
                         :: "r"(bbase + br * ROWB + quad * 16), "l"(src));
        }
    }
}

__global__ void __launch_bounds__(256, 1) k_gemm(const float* __restrict__ bias,
                                                 const float* __restrict__ anchors) {
    extern __shared__ char smem[];
    uint32_t sb = smem_u32(smem);
    const int tid  = threadIdx.x;
    const int lane = tid & 31;
    const int warp = tid >> 5;
    const int bm = blockIdx.y * MT;
    const int bn = blockIdx.x * NT;
    const int wm = (warp >> 2) * 64;   // 2 M-warps
    const int wn = (warp & 3) * 64;    // 4 N-warps

    float acc[4][8][4];
    #pragma unroll
    for (int mi = 0; mi < 4; mi++)
        #pragma unroll
        for (int ni = 0; ni < 8; ni++)
            #pragma unroll
            for (int q = 0; q < 4; q++) acc[mi][ni][q] = 0.f;

    const __half* Xp = g_xh + (size_t)bm * DIM;
    const __half* Wp = g_wh + (size_t)bn * DIM;

    const int g  = lane >> 2;
    const int tg = lane & 3;

    const uint32_t a_row  = wm + (lane & 15);
    const uint32_t a_koff = (lane >> 4) * 16;
    const uint32_t b_row  = wn + ((lane >> 4) << 3) + (lane & 7);
    const uint32_t b_koff = ((lane >> 3) & 1) * 16;

    load_stage(sb, 0, 0, Xp, Wp, tid);
    asm volatile("cp.async.commit_group;" ::: "memory");
    load_stage(sb, 1, 1, Xp, Wp, tid);
    asm volatile("cp.async.commit_group;" ::: "memory");
    load_stage(sb, 2, 2, Xp, Wp, tid);
    asm volatile("cp.async.commit_group;" ::: "memory");

    for (int i = 0; i < NITER; i++) {
        asm volatile("cp.async.wait_group 2;" ::: "memory");
        __syncthreads();
        if (i + 3 < NITER)
            load_stage(sb, (i + 3) & 3, i + 3, Xp, Wp, tid);
        asm volatile("cp.async.commit_group;" ::: "memory");

        uint32_t abase = sb + (i & 3) * STAGE_BYTES;
        uint32_t bbase = abase + A_STAGE_BYTES;

        #pragma unroll
        for (int ks = 0; ks < 2; ks++) {
            uint32_t a[4][4];
            #pragma unroll
            for (int mi = 0; mi < 4; mi++)
                ldsm4(abase + (a_row + mi * 16) * ROWB + ks * 32 + a_koff,
                      a[mi][0], a[mi][1], a[mi][2], a[mi][3]);
            uint32_t b[8][2];
            #pragma unroll
            for (int p = 0; p < 4; p++)
                ldsm4(bbase + (b_row + p * 16) * ROWB + ks * 32 + b_koff,
                      b[2 * p][0], b[2 * p][1], b[2 * p + 1][0], b[2 * p + 1][1]);
            #pragma unroll
            for (int mi = 0; mi < 4; mi++)
                #pragma unroll
                for (int ni = 0; ni < 8; ni++) {
                    asm volatile(
                        "mma.sync.aligned.m16n8k16.row.col.f32.f16.f16.f32 "
                        "{%0,%1,%2,%3}, {%4,%5,%6,%7}, {%8,%9}, {%0,%1,%2,%3};\n"
                        : "+f"(acc[mi][ni][0]), "+f"(acc[mi][ni][1]),
                          "+f"(acc[mi][ni][2]), "+f"(acc[mi][ni][3])
                        : "r"(a[mi][0]), "r"(a[mi][1]), "r"(a[mi][2]), "r"(a[mi][3]),
                          "r"(b[ni][0]), "r"(b[ni][1]));
                }
        }
    }

    // Epilogue: h = s_row * acc/1024 + bias; store + per-row partial sums
    float sc = g_sc;
    float bz0[8], bz1[8];
    #pragma unroll
    for (int ni = 0; ni < 8; ni++) {
        int cc = bn + wn + ni * 8 + tg * 2;
        bz0[ni] = bias[cc];
        bz1[ni] = bias[cc + 1];
    }
    #pragma unroll
    for (int mi = 0; mi < 4; mi++) {
        int r0 = bm + wm + mi * 16 + g;
        float s0 = row_scale(r0, sc) * SCALE_INV;
        float s1 = row_scale(r0 + 8, sc) * SCALE_INV;
        float p0[5] = {0.f, 0.f, 0.f, 0.f, 0.f};
        float p1[5] = {0.f, 0.f, 0.f, 0.f, 0.f};
        #pragma unroll
        for (int ni = 0; ni < 8; ni++) {
            int cc = bn + wn + ni * 8 + tg * 2;
            float h00 = fmaf(s0, acc[mi][ni][0], bz0[ni]);
            float h01 = fmaf(s0, acc[mi][ni][1], bz1[ni]);
            float h10 = fmaf(s1, acc[mi][ni][2], bz0[ni]);
            float h11 = fmaf(s1, acc[mi][ni][3], bz1[ni]);
            float* o0 = g_h + (size_t)r0 * DIM + cc;
            o0[0] = h00; o0[1] = h01;
            float* o1 = g_h + (size_t)(r0 + 8) * DIM + cc;
            o1[0] = h10; o1[1] = h11;
            p0[0] += h00 * h00 + h01 * h01;
            p1[0] += h10 * h10 + h11 * h11;
            #pragma unroll
            for (int k = 0; k < NK; k++) {
                float a0 = anchors[k * DIM + cc];
                float a1 = anchors[k * DIM + cc + 1];
                p0[1 + k] += h00 * a0 + h01 * a1;
                p1[1 + k] += h10 * a0 + h11 * a1;
            }
        }
        #pragma unroll
        for (int q = 0; q < 5; q++) {
            p0[q] += __shfl_xor_sync(0xffffffffu, p0[q], 1);
            p0[q] += __shfl_xor_sync(0xffffffffu, p0[q], 2);
            p1[q] += __shfl_xor_sync(0xffffffffu, p1[q], 1);
            p1[q] += __shfl_xor_sync(0xffffffffu, p1[q], 2);
        }
        if (tg == 0) {
            int pi = blockIdx.x * 4 + (warp & 3);     // 8 n-blocks * 4 n-warps = 32
            float* d0 = g_part + ((size_t)r0 * 32 + pi) * 5;
            float* d1 = g_part + ((size_t)(r0 + 8) * 32 + pi) * 5;
            #pragma unroll
            for (int q = 0; q < 5; q++) { d0[q] = p0[q]; d1[q] = p1[q]; }
        }
    }
}

// ------------------------------------------------------------------
// Kernel 3b: per-row coefficients from partial sums
// ------------------------------------------------------------------
__global__ __launch_bounds__(256) void k_coef(const float* __restrict__ tv) {
    int row = blockIdx.x * 256 + threadIdx.x;
    const float* pp = g_part + (size_t)row * 160;
    float red[5] = {0.f, 0.f, 0.f, 0.f, 0.f};
    for (int p = 0; p < 32; p++)
        #pragma unroll
        for (int q = 0; q < 5; q++) red[q] += pp[p * 5 + q];

    float c = g_c, sc = g_sc;
    float h2 = red[0];
    float m = fmaxf(sqrtf(h2), EPSF);
    float scm = sc * m;
    float e = tanhf(scm) / scm;
    float y2 = e * e * h2;

    float Acoef = 0.f;
    #pragma unroll
    for (int k = 0; k < NK; k++) {
        float ya  = e * red[1 + k];
        float an2 = g_an2[k];
        float P  = 1.f - 2.f * c * ya + c * an2;
        float Q  = 1.f - c * y2;
        float D1 = fmaxf(1.f - 2.f * c * ya + c * c * y2 * an2, EPSF);
        float diff2 = (P * P * y2 - 2.f * P * Q * ya + Q * Q * an2) / (D1 * D1);
        float nd = fmaxf(sqrtf(fmaxf(diff2, 0.f)), EPSF);
        float z  = sc * nd;
        float ar = atanhf(clip_artanh_arg(z));
        float tau = tanhf(tv[k] * ar) / z;
        float uy = -tau * P / D1;
        float ua =  tau * Q / D1;
        float xys = uy * y2 + ua * ya;
        float y2s = tau * tau * diff2;
        float den2 = fmaxf(1.f + 2.f * c * xys + c * c * y2 * y2s, EPSF);
        float alpha = (1.f + 2.f * c * xys + c * y2s + (1.f - c * y2) * uy) / den2;
        float beta  = (1.f - c * y2) * ua / den2;
        float w2 = g_w[k];
        Acoef += w2 * alpha;
        g_Bco[row * NK + k] = w2 * beta;
    }
    g_Ae[row] = Acoef * e;
}

// ------------------------------------------------------------------
// Kernel 4: pure streaming combine  out = Ae*h + sum_k Bk*a_k
// ------------------------------------------------------------------
__global__ __launch_bounds__(256) void k_final(const float* __restrict__ anchors,
                                               float* __restrict__ out) {
    int row = blockIdx.x;
    float Ae = g_Ae[row];
    float B0 = g_Bco[row * NK + 0];
    float B1 = g_Bco[row * NK + 1];
    float B2 = g_Bco[row * NK + 2];
    float B3 = g_Bco[row * NK + 3];
    const float4* hr = (const float4*)(g_h + (size_t)row * DIM);
    const float4* a0 = (const float4*)(anchors);
    const float4* a1 = (const float4*)(anchors + DIM);
    const float4* a2 = (const float4*)(anchors + 2 * DIM);
    const float4* a3 = (const float4*)(anchors + 3 * DIM);
    float4* outr = (float4*)(out + (size_t)row * DIM);
    #pragma unroll
    for (int i = 0; i < 2; i++) {
        int idx = threadIdx.x + i * 256;
        float4 h = hr[idx];
        float4 v0 = a0[idx], v1 = a1[idx], v2 = a2[idx], v3 = a3[idx];
        float4 o;
        o.x = Ae * h.x; o.y = Ae * h.y; o.z = Ae * h.z; o.w = Ae * h.w;
        o.x = fmaf(B0, v0.x, o.x); o.y = fmaf(B0, v0.y, o.y);
        o.z = fmaf(B0, v0.z, o.z); o.w = fmaf(B0, v0.w, o.w);
        o.x = fmaf(B1, v1.x, o.x); o.y = fmaf(B1, v1.y, o.y);
        o.z = fmaf(B1, v1.z, o.z); o.w = fmaf(B1, v1.w, o.w);
        o.x = fmaf(B2, v2.x, o.x); o.y = fmaf(B2, v2.y, o.y);
        o.z = fmaf(B2, v2.z, o.z); o.w = fmaf(B2, v2.w, o.w);
        o.x = fmaf(B3, v3.x, o.x); o.y = fmaf(B3, v3.y, o.y);
        o.z = fmaf(B3, v3.z, o.z); o.w = fmaf(B3, v3.w, o.w);
        outr[idx] = o;
    }
}

// ------------------------------------------------------------------
// Launch
// ------------------------------------------------------------------
extern "C" void kernel_launch(void* const* d_in, const int* in_sizes, int n_in,
                              void* d_out, int out_size) {
    const float* x       = (const float*)d_in[0];
    const float* weight  = (const float*)d_in[1];
    const float* bias    = (const float*)d_in[2];
    const float* cw      = (const float*)d_in[3];
    const float* cb      = (const float*)d_in[4];
    const float* anchors = (const float*)d_in[5];
    const float* tv      = (const float*)d_in[6];
    const float* aw      = (const float*)d_in[7];
    float* out = (float*)d_out;

    cudaFuncSetAttribute(k_gemm, cudaFuncAttributeMaxDynamicSharedMemorySize,
                         SMEM_TOTAL);

    k_rowstat<<<NROWS, 256>>>(x, cw, cb);
    k_cvtW<<<DIM * DIM / 4 / 256, 256>>>(weight);
    k_scalars<<<1, 256>>>(anchors, aw);
    dim3 grid(DIM / NT, NROWS / MT);       // 8 x 32 = 256 CTAs
    k_gemm<<<grid, 256, SMEM_TOTAL>>>(bias, anchors);
    k_coef<<<NROWS / 256, 256>>>(tv);
    k_final<<<NROWS, 256>>>(anchors, out);
}

// round 8
// speedup vs baseline: 2.1476x; 1.2848x over previous
#include <cuda_runtime.h>
#include <cuda_fp16.h>
#include <cuda.h>
#include <cstdint>
#include <math.h>

#define NROWS 4096
#define DIM   2048
#define NK    4
#define EPSF  1e-6f

// GEMM tiling (fp16, mma.m16n8k16), block 128x256, warp 64x64, 8 warps
#define MT 128
#define NT 256
#define KC 64                     // K halves per stage (128B rows -> SW128)
#define NSTAGE 4
#define NITER (DIM / KC)          // 32
#define A_STAGE_BYTES (MT * 128)               // 16384
#define B_STAGE_BYTES (NT * 128)               // 32768
#define STAGE_BYTES   (A_STAGE_BYTES + B_STAGE_BYTES)   // 49152
#define SOFF_MBAR     (NSTAGE * STAGE_BYTES)   // 196608
#define SMEM_TOTAL    (SOFF_MBAR + 64)

#define SCALE     32.0f
#define SCALE_INV 9.765625e-4f    // 1/1024

// ------------------------------------------------------------------
// Device scratch
// ------------------------------------------------------------------
__device__ float  g_h[(size_t)NROWS * DIM];
__device__ __half g_xh[(size_t)NROWS * DIM];
__device__ __half g_wh[(size_t)DIM * DIM];
__device__ float  g_part[(size_t)NROWS * 32 * 5];
__device__ float  g_Ae[NROWS];
__device__ float  g_Bco[NROWS * NK];
__device__ float  g_xn2[NROWS];
__device__ float  g_sp[NROWS];
__device__ float  g_c;
__device__ float  g_sc;
__device__ float  g_an2[NK];
__device__ float  g_w[NK];

// ------------------------------------------------------------------
// Helpers
// ------------------------------------------------------------------
__device__ __forceinline__ uint32_t smem_u32(const void* p) {
    uint32_t a;
    asm("{ .reg .u64 t; cvta.to.shared.u64 t, %1; cvt.u32.u64 %0, t; }"
        : "=r"(a) : "l"(p));
    return a;
}

__device__ __forceinline__ float blockReduceSum(float v, float* sbuf) {
    #pragma unroll
    for (int o = 16; o > 0; o >>= 1) v += __shfl_xor_sync(0xffffffffu, v, o);
    int w = threadIdx.x >> 5;
    if ((threadIdx.x & 31) == 0) sbuf[w] = v;
    __syncthreads();
    if (threadIdx.x < 32) {
        float t = (threadIdx.x < 8) ? sbuf[threadIdx.x] : 0.f;
        #pragma unroll
        for (int o = 4; o > 0; o >>= 1) t += __shfl_xor_sync(0xffffffffu, t, o);
        if (threadIdx.x == 0) sbuf[0] = t;
    }
    __syncthreads();
    float r = sbuf[0];
    __syncthreads();
    return r;
}

__device__ __forceinline__ float clip_artanh_arg(float z) {
    return fminf(fmaxf(z, -1.f + 1e-5f), 1.f - 1e-5f);
}

__device__ __forceinline__ void ldsm4(uint32_t addr, uint32_t& r0, uint32_t& r1,
                                      uint32_t& r2, uint32_t& r3) {
    asm volatile("ldmatrix.sync.aligned.m8n8.x4.shared.b16 {%0,%1,%2,%3}, [%4];"
                 : "=r"(r0), "=r"(r1), "=r"(r2), "=r"(r3) : "r"(addr));
}

__device__ __forceinline__ void mbar_init(uint32_t a, uint32_t cnt) {
    asm volatile("mbarrier.init.shared.b64 [%0], %1;" :: "r"(a), "r"(cnt) : "memory");
}

__device__ __forceinline__ void mbar_expect(uint32_t a, uint32_t bytes) {
    asm volatile("mbarrier.arrive.expect_tx.shared.b64 _, [%0], %1;"
                 :: "r"(a), "r"(bytes) : "memory");
}

__device__ __forceinline__ void mbar_wait(uint32_t a, uint32_t parity) {
    asm volatile(
        "{\n\t"
        ".reg .pred P;\n\t"
        "W%=:\n\t"
        "mbarrier.try_wait.parity.acquire.cta.shared::cta.b64 P, [%0], %1;\n\t"
        "@P bra D%=;\n\t"
        "bra W%=;\n\t"
        "D%=:\n\t"
        "}"
        :: "r"(a), "r"(parity) : "memory");
}

__device__ __forceinline__ void tma2d(uint32_t dst, const CUtensorMap* map,
                                      int cx, int cy, uint32_t mbar) {
    asm volatile(
        "cp.async.bulk.tensor.2d.shared::cta.global.tile.mbarrier::complete_tx::bytes "
        "[%0], [%1, {%2, %3}], [%4];"
        :: "r"(dst), "l"(map), "r"(cx), "r"(cy), "r"(mbar) : "memory");
}

// ------------------------------------------------------------------
// Kernel 1: per-row |x|^2, softplus(x.cw+cb), fp16 (x*32) copy
// ------------------------------------------------------------------
__global__ __launch_bounds__(256) void k_rowstat(const float* __restrict__ x,
                                                 const float* __restrict__ cw,
                                                 const float* __restrict__ cb) {
    int row = blockIdx.x;
    const float4* xr = (const float4*)(x + (size_t)row * DIM);
    const float4* cr = (const float4*)cw;
    __half2* xo = (__half2*)(g_xh + (size_t)row * DIM);
    float dot = 0.f, nn = 0.f;
    #pragma unroll
    for (int i = 0; i < 2; i++) {
        int idx = threadIdx.x + i * 256;
        float4 a = xr[idx], b = cr[idx];
        dot += a.x * b.x + a.y * b.y + a.z * b.z + a.w * b.w;
        nn  += a.x * a.x + a.y * a.y + a.z * a.z + a.w * a.w;
        xo[idx * 2]     = __floats2half2_rn(a.x * SCALE, a.y * SCALE);
        xo[idx * 2 + 1] = __floats2half2_rn(a.z * SCALE, a.w * SCALE);
    }
    __shared__ float sbuf[8];
    dot = blockReduceSum(dot, sbuf);
    nn  = blockReduceSum(nn, sbuf);
    if (threadIdx.x == 0) {
        g_xn2[row] = nn;
        float l = dot + cb[0];
        g_sp[row] = fmaxf(l, 0.f) + log1pf(expf(-fabsf(l)));
    }
}

// ------------------------------------------------------------------
// Kernel 1b: W -> fp16 (w*32)
// ------------------------------------------------------------------
__global__ __launch_bounds__(256) void k_cvtW(const float* __restrict__ W) {
    int i = blockIdx.x * 256 + threadIdx.x;
    float4 v = ((const float4*)W)[i];
    __half2* o = (__half2*)g_wh;
    o[i * 2]     = __floats2half2_rn(v.x * SCALE, v.y * SCALE);
    o[i * 2 + 1] = __floats2half2_rn(v.z * SCALE, v.w * SCALE);
}

// ------------------------------------------------------------------
// Kernel 2: scalars
// ------------------------------------------------------------------
__global__ __launch_bounds__(256) void k_scalars(const float* __restrict__ anchors,
                                                 const float* __restrict__ aw) {
    __shared__ float sbuf[8];
    float s = 0.f;
    for (int i = threadIdx.x; i < NROWS; i += 256) s += g_sp[i];
    s = blockReduceSum(s, sbuf);
    float c = s / (float)NROWS;

    for (int k = 0; k < NK; k++) {
        float v = 0.f;
        for (int j = threadIdx.x; j < DIM; j += 256) {
            float a = anchors[k * DIM + j];
            v += a * a;
        }
        v = blockReduceSum(v, sbuf);
        if (threadIdx.x == 0) g_an2[k] = v;
    }

    if (threadIdx.x == 0) {
        g_c = c;
        g_sc = sqrtf(c);
        float m = fmaxf(fmaxf(aw[0], aw[1]), fmaxf(aw[2], aw[3]));
        float e0 = expf(aw[0] - m), e1 = expf(aw[1] - m);
        float e2 = expf(aw[2] - m), e3 = expf(aw[3] - m);
        float inv = 1.f / (e0 + e1 + e2 + e3);
        g_w[0] = e0 * inv; g_w[1] = e1 * inv;
        g_w[2] = e2 * inv; g_w[3] = e3 * inv;
    }
}

// ------------------------------------------------------------------
// Kernel 3: TMA-fed fp16 mma.sync GEMM (128x256 block, 64x64 warps)
// ------------------------------------------------------------------
__device__ __forceinline__ float row_scale(int r, float sc) {
    float n = fmaxf(sqrtf(g_xn2[r]), EPSF);
    float z = sc * n;
    return atanhf(clip_artanh_arg(z)) / z;
}

__global__ void __launch_bounds__(256, 1) k_gemm(
    const __grid_constant__ CUtensorMap xmap,
    const __grid_constant__ CUtensorMap wmap,
    const float* __restrict__ bias,
    const float* __restrict__ anchors)
{
    extern __shared__ char smem[];
    uint32_t sb = smem_u32(smem);
    const int tid  = threadIdx.x;
    const int lane = tid & 31;
    const int warp = tid >> 5;
    const int bm = blockIdx.y * MT;
    const int bn = blockIdx.x * NT;
    const int wm = (warp >> 2) * 64;   // 2 M-warps
    const int wn = (warp & 3) * 64;    // 4 N-warps
    const uint32_t mb = sb + SOFF_MBAR;

    float acc[4][8][4];
    #pragma unroll
    for (int mi = 0; mi < 4; mi++)
        #pragma unroll
        for (int ni = 0; ni < 8; ni++)
            #pragma unroll
            for (int q = 0; q < 4; q++) acc[mi][ni][q] = 0.f;

    const int g  = lane >> 2;
    const int tg = lane & 3;

    // ldmatrix per-lane addressing (SW128 swizzle: row*128 + (kb ^ ((row&7)<<4)))
    const uint32_t a_row = wm + (lane & 15);
    const uint32_t aq    = ((lane >> 4) * 16) ^ ((a_row & 7) << 4);
    const uint32_t b_row = wn + ((lane >> 4) << 3) + (lane & 7);
    const uint32_t bq    = (((lane >> 3) & 1) * 16) ^ ((b_row & 7) << 4);

    if (tid == 0) {
        #pragma unroll
        for (int s = 0; s < NSTAGE; s++) mbar_init(mb + 8 * s, 1);
    }
    __syncthreads();
    if (tid == 0) {
        #pragma unroll
        for (int s = 0; s < 3; s++) {
            uint32_t abase = sb + s * STAGE_BYTES;
            mbar_expect(mb + 8 * s, STAGE_BYTES);
            tma2d(abase, &xmap, s * KC, bm, mb + 8 * s);
            tma2d(abase + A_STAGE_BYTES, &wmap, s * KC, bn, mb + 8 * s);
        }
    }

    for (int i = 0; i < NITER; i++) {
        int s = i & 3;
        mbar_wait(mb + 8 * s, (i >> 2) & 1);
        uint32_t abase = sb + s * STAGE_BYTES;
        uint32_t bbase = abase + A_STAGE_BYTES;

        #pragma unroll
        for (int ks = 0; ks < 4; ks++) {
            uint32_t a[4][4];
            #pragma unroll
            for (int mi = 0; mi < 4; mi++)
                ldsm4(abase + (a_row + mi * 16) * 128 + ((ks * 32) ^ aq),
                      a[mi][0], a[mi][1], a[mi][2], a[mi][3]);
            uint32_t b[8][2];
            #pragma unroll
            for (int p = 0; p < 4; p++)
                ldsm4(bbase + (b_row + p * 16) * 128 + ((ks * 32) ^ bq),
                      b[2 * p][0], b[2 * p][1], b[2 * p + 1][0], b[2 * p + 1][1]);
            #pragma unroll
            for (int mi = 0; mi < 4; mi++)
                #pragma unroll
                for (int ni = 0; ni < 8; ni++) {
                    asm volatile(
                        "mma.sync.aligned.m16n8k16.row.col.f32.f16.f16.f32 "
                        "{%0,%1,%2,%3}, {%4,%5,%6,%7}, {%8,%9}, {%0,%1,%2,%3};\n"
                        : "+f"(acc[mi][ni][0]), "+f"(acc[mi][ni][1]),
                          "+f"(acc[mi][ni][2]), "+f"(acc[mi][ni][3])
                        : "r"(a[mi][0]), "r"(a[mi][1]), "r"(a[mi][2]), "r"(a[mi][3]),
                          "r"(b[ni][0]), "r"(b[ni][1]));
                }
        }
        __syncthreads();   // all warps done reading stage (i-1)'s buffer family
        if (tid == 0 && i + 3 < NITER) {
            int j = i + 3, s2 = j & 3;
            uint32_t ab2 = sb + s2 * STAGE_BYTES;
            mbar_expect(mb + 8 * s2, STAGE_BYTES);
            tma2d(ab2, &xmap, j * KC, bm, mb + 8 * s2);
            tma2d(ab2 + A_STAGE_BYTES, &wmap, j * KC, bn, mb + 8 * s2);
        }
    }

    // Epilogue: h = s_row * acc/1024 + bias; store + per-row partial sums
    float sc = g_sc;
    float bz0[8], bz1[8];
    #pragma unroll
    for (int ni = 0; ni < 8; ni++) {
        int cc = bn + wn + ni * 8 + tg * 2;
        bz0[ni] = bias[cc];
        bz1[ni] = bias[cc + 1];
    }
    #pragma unroll
    for (int mi = 0; mi < 4; mi++) {
        int r0 = bm + wm + mi * 16 + g;
        float s0 = row_scale(r0, sc) * SCALE_INV;
        float s1 = row_scale(r0 + 8, sc) * SCALE_INV;
        float p0[5] = {0.f, 0.f, 0.f, 0.f, 0.f};
        float p1[5] = {0.f, 0.f, 0.f, 0.f, 0.f};
        #pragma unroll
        for (int ni = 0; ni < 8; ni++) {
            int cc = bn + wn + ni * 8 + tg * 2;
            float h00 = fmaf(s0, acc[mi][ni][0], bz0[ni]);
            float h01 = fmaf(s0, acc[mi][ni][1], bz1[ni]);
            float h10 = fmaf(s1, acc[mi][ni][2], bz0[ni]);
            float h11 = fmaf(s1, acc[mi][ni][3], bz1[ni]);
            float* o0 = g_h + (size_t)r0 * DIM + cc;
            o0[0] = h00; o0[1] = h01;
            float* o1 = g_h + (size_t)(r0 + 8) * DIM + cc;
            o1[0] = h10; o1[1] = h11;
            p0[0] += h00 * h00 + h01 * h01;
            p1[0] += h10 * h10 + h11 * h11;
            #pragma unroll
            for (int k = 0; k < NK; k++) {
                float a0 = anchors[k * DIM + cc];
                float a1 = anchors[k * DIM + cc + 1];
                p0[1 + k] += h00 * a0 + h01 * a1;
                p1[1 + k] += h10 * a0 + h11 * a1;
            }
        }
        #pragma unroll
        for (int q = 0; q < 5; q++) {
            p0[q] += __shfl_xor_sync(0xffffffffu, p0[q], 1);
            p0[q] += __shfl_xor_sync(0xffffffffu, p0[q], 2);
            p1[q] += __shfl_xor_sync(0xffffffffu, p1[q], 1);
            p1[q] += __shfl_xor_sync(0xffffffffu, p1[q], 2);
        }
        if (tg == 0) {
            int pi = blockIdx.x * 4 + (warp & 3);     // 8 n-blocks * 4 n-warps = 32
            float* d0 = g_part + ((size_t)r0 * 32 + pi) * 5;
            float* d1 = g_part + ((size_t)(r0 + 8) * 32 + pi) * 5;
            #pragma unroll
            for (int q = 0; q < 5; q++) { d0[q] = p0[q]; d1[q] = p1[q]; }
        }
    }
}

// ------------------------------------------------------------------
// Kernel 3b: per-row coefficients from partial sums
// ------------------------------------------------------------------
__global__ __launch_bounds__(256) void k_coef(const float* __restrict__ tv) {
    int row = blockIdx.x * 256 + threadIdx.x;
    const float* pp = g_part + (size_t)row * 160;
    float red[5] = {0.f, 0.f, 0.f, 0.f, 0.f};
    for (int p = 0; p < 32; p++)
        #pragma unroll
        for (int q = 0; q < 5; q++) red[q] += pp[p * 5 + q];

    float c = g_c, sc = g_sc;
    float h2 = red[0];
    float m = fmaxf(sqrtf(h2), EPSF);
    float scm = sc * m;
    float e = tanhf(scm) / scm;
    float y2 = e * e * h2;

    float Acoef = 0.f;
    #pragma unroll
    for (int k = 0; k < NK; k++) {
        float ya  = e * red[1 + k];
        float an2 = g_an2[k];
        float P  = 1.f - 2.f * c * ya + c * an2;
        float Q  = 1.f - c * y2;
        float D1 = fmaxf(1.f - 2.f * c * ya + c * c * y2 * an2, EPSF);
        float diff2 = (P * P * y2 - 2.f * P * Q * ya + Q * Q * an2) / (D1 * D1);
        float nd = fmaxf(sqrtf(fmaxf(diff2, 0.f)), EPSF);
        float z  = sc * nd;
        float ar = atanhf(clip_artanh_arg(z));
        float tau = tanhf(tv[k] * ar) / z;
        float uy = -tau * P / D1;
        float ua =  tau * Q / D1;
        float xys = uy * y2 + ua * ya;
        float y2s = tau * tau * diff2;
        float den2 = fmaxf(1.f + 2.f * c * xys + c * c * y2 * y2s, EPSF);
        float alpha = (1.f + 2.f * c * xys + c * y2s + (1.f - c * y2) * uy) / den2;
        float beta  = (1.f - c * y2) * ua / den2;
        float w2 = g_w[k];
        Acoef += w2 * alpha;
        g_Bco[row * NK + k] = w2 * beta;
    }
    g_Ae[row] = Acoef * e;
}

// ------------------------------------------------------------------
// Kernel 4: pure streaming combine  out = Ae*h + sum_k Bk*a_k
// ------------------------------------------------------------------
__global__ __launch_bounds__(256) void k_final(const float* __restrict__ anchors,
                                               float* __restrict__ out) {
    int row = blockIdx.x;
    float Ae = g_Ae[row];
    float B0 = g_Bco[row * NK + 0];
    float B1 = g_Bco[row * NK + 1];
    float B2 = g_Bco[row * NK + 2];
    float B3 = g_Bco[row * NK + 3];
    const float4* hr = (const float4*)(g_h + (size_t)row * DIM);
    const float4* a0 = (const float4*)(anchors);
    const float4* a1 = (const float4*)(anchors + DIM);
    const float4* a2 = (const float4*)(anchors + 2 * DIM);
    const float4* a3 = (const float4*)(anchors + 3 * DIM);
    float4* outr = (float4*)(out + (size_t)row * DIM);
    #pragma unroll
    for (int i = 0; i < 2; i++) {
        int idx = threadIdx.x + i * 256;
        float4 h = hr[idx];
        float4 v0 = a0[idx], v1 = a1[idx], v2 = a2[idx], v3 = a3[idx];
        float4 o;
        o.x = Ae * h.x; o.y = Ae * h.y; o.z = Ae * h.z; o.w = Ae * h.w;
        o.x = fmaf(B0, v0.x, o.x); o.y = fmaf(B0, v0.y, o.y);
        o.z = fmaf(B0, v0.z, o.z); o.w = fmaf(B0, v0.w, o.w);
        o.x = fmaf(B1, v1.x, o.x); o.y = fmaf(B1, v1.y, o.y);
        o.z = fmaf(B1, v1.z, o.z); o.w = fmaf(B1, v1.w, o.w);
        o.x = fmaf(B2, v2.x, o.x); o.y = fmaf(B2, v2.y, o.y);
        o.z = fmaf(B2, v2.z, o.z); o.w = fmaf(B2, v2.w, o.w);
        o.x = fmaf(B3, v3.x, o.x); o.y = fmaf(B3, v3.y, o.y);
        o.z = fmaf(B3, v3.z, o.z); o.w = fmaf(B3, v3.w, o.w);
        outr[idx] = o;
    }
}

// ------------------------------------------------------------------
// Launch
// ------------------------------------------------------------------
typedef CUresult (*tmapEncodeFn)(
    CUtensorMap*, CUtensorMapDataType, cuuint32_t, void*,
    const cuuint64_t*, const cuuint64_t*, const cuuint32_t*, const cuuint32_t*,
    CUtensorMapInterleave, CUtensorMapSwizzle, CUtensorMapL2promotion,
    CUtensorMapFloatOOBfill);

extern "C" void kernel_launch(void* const* d_in, const int* in_sizes, int n_in,
                              void* d_out, int out_size) {
    const float* x       = (const float*)d_in[0];
    const float* weight  = (const float*)d_in[1];
    const float* bias    = (const float*)d_in[2];
    const float* cw      = (const float*)d_in[3];
    const float* cb      = (const float*)d_in[4];
    const float* anchors = (const float*)d_in[5];
    const float* tv      = (const float*)d_in[6];
    const float* aw      = (const float*)d_in[7];
    float* out = (float*)d_out;

    cudaFuncSetAttribute(k_gemm, cudaFuncAttributeMaxDynamicSharedMemorySize,
                         SMEM_TOTAL);

    // Build tensor maps for the fp16 scratch tensors
    void* xptr = nullptr;
    void* wptr = nullptr;
    cudaGetSymbolAddress(&xptr, g_xh);
    cudaGetSymbolAddress(&wptr, g_wh);

    tmapEncodeFn encode = nullptr;
    cudaDriverEntryPointQueryResult qr;
    cudaGetDriverEntryPointByVersion("cuTensorMapEncodeTiled", (void**)&encode,
                                     12000, cudaEnableDefault, &qr);

    CUtensorMap xmap, wmap;
    {
        cuuint64_t gdim[2] = {DIM, NROWS};
        cuuint64_t gstr[1] = {DIM * 2};           // bytes between rows
        cuuint32_t box[2]  = {KC, MT};            // 64 halves x 128 rows
        cuuint32_t est[2]  = {1, 1};
        encode(&xmap, CU_TENSOR_MAP_DATA_TYPE_UINT16, 2, xptr,
               gdim, gstr, box, est,
               CU_TENSOR_MAP_INTERLEAVE_NONE, CU_TENSOR_MAP_SWIZZLE_128B,
               CU_TENSOR_MAP_L2_PROMOTION_L2_128B,
               CU_TENSOR_MAP_FLOAT_OOB_FILL_NONE);
    }
    {
        cuuint64_t gdim[2] = {DIM, DIM};
        cuuint64_t gstr[1] = {DIM * 2};
        cuuint32_t box[2]  = {KC, NT};            // 64 halves x 256 rows
        cuuint32_t est[2]  = {1, 1};
        encode(&wmap, CU_TENSOR_MAP_DATA_TYPE_UINT16, 2, wptr,
               gdim, gstr, box, est,
               CU_TENSOR_MAP_INTERLEAVE_NONE, CU_TENSOR_MAP_SWIZZLE_128B,
               CU_TENSOR_MAP_L2_PROMOTION_L2_128B,
               CU_TENSOR_MAP_FLOAT_OOB_FILL_NONE);
    }

    k_rowstat<<<NROWS, 256>>>(x, cw, cb);
    k_cvtW<<<DIM * DIM / 4 / 256, 256>>>(weight);
    k_scalars<<<1, 256>>>(anchors, aw);
    dim3 grid(DIM / NT, NROWS / MT);       // 8 x 32 = 256 CTAs
    k_gemm<<<grid, 256, SMEM_TOTAL>>>(xmap, wmap, bias, anchors);
    k_coef<<<NROWS / 256, 256>>>(tv);
    k_final<<<NROWS, 256>>>(anchors, out);
}

// round 9
// speedup vs baseline: 2.2569x; 1.0509x over previous
#include <cuda_runtime.h>
#include <cuda_fp16.h>
#include <cuda.h>
#include <cstdint>
#include <math.h>

#define NROWS 4096
#define DIM   2048
#define NK    4
#define EPSF  1e-6f

// GEMM tiling (fp16, mma.m16n8k16), block 128x256, warp 64x32, 16 warps
#define MT 128
#define NT 256
#define KC 64                     // K halves per stage (128B rows -> SW128)
#define NSTAGE 4
#define NITER (DIM / KC)          // 32
#define A_STAGE_BYTES (MT * 128)               // 16384
#define B_STAGE_BYTES (NT * 128)               // 32768
#define STAGE_BYTES   (A_STAGE_BYTES + B_STAGE_BYTES)   // 49152
#define SOFF_MBAR     (NSTAGE * STAGE_BYTES)   // 196608
#define SMEM_TOTAL    (SOFF_MBAR + 64)

#define NPART 64                  // per-row partial slots (8 n-blocks * 8 n-warps)

#define SCALE     32.0f
#define SCALE_INV 9.765625e-4f    // 1/1024

// ------------------------------------------------------------------
// Device scratch
// ------------------------------------------------------------------
__device__ float  g_h[(size_t)NROWS * DIM];
__device__ __half g_xh[(size_t)NROWS * DIM];
__device__ __half g_wh[(size_t)DIM * DIM];
__device__ float  g_part[(size_t)NROWS * NPART * 5];
__device__ float  g_xn2[NROWS];
__device__ float  g_sp[NROWS];
__device__ float  g_c;
__device__ float  g_sc;
__device__ float  g_an2[NK];
__device__ float  g_w[NK];

// ------------------------------------------------------------------
// Helpers
// ------------------------------------------------------------------
__device__ __forceinline__ uint32_t smem_u32(const void* p) {
    uint32_t a;
    asm("{ .reg .u64 t; cvta.to.shared.u64 t, %1; cvt.u32.u64 %0, t; }"
        : "=r"(a) : "l"(p));
    return a;
}

__device__ __forceinline__ float blockReduceSum(float v, float* sbuf) {
    #pragma unroll
    for (int o = 16; o > 0; o >>= 1) v += __shfl_xor_sync(0xffffffffu, v, o);
    int w = threadIdx.x >> 5;
    if ((threadIdx.x & 31) == 0) sbuf[w] = v;
    __syncthreads();
    if (threadIdx.x < 32) {
        float t = (threadIdx.x < 8) ? sbuf[threadIdx.x] : 0.f;
        #pragma unroll
        for (int o = 4; o > 0; o >>= 1) t += __shfl_xor_sync(0xffffffffu, t, o);
        if (threadIdx.x == 0) sbuf[0] = t;
    }
    __syncthreads();
    float r = sbuf[0];
    __syncthreads();
    return r;
}

__device__ __forceinline__ float clip_artanh_arg(float z) {
    return fminf(fmaxf(z, -1.f + 1e-5f), 1.f - 1e-5f);
}

__device__ __forceinline__ void ldsm4(uint32_t addr, uint32_t& r0, uint32_t& r1,
                                      uint32_t& r2, uint32_t& r3) {
    asm volatile("ldmatrix.sync.aligned.m8n8.x4.shared.b16 {%0,%1,%2,%3}, [%4];"
                 : "=r"(r0), "=r"(r1), "=r"(r2), "=r"(r3) : "r"(addr));
}

__device__ __forceinline__ void mbar_init(uint32_t a, uint32_t cnt) {
    asm volatile("mbarrier.init.shared.b64 [%0], %1;" :: "r"(a), "r"(cnt) : "memory");
}

__device__ __forceinline__ void mbar_expect(uint32_t a, uint32_t bytes) {
    asm volatile("mbarrier.arrive.expect_tx.shared.b64 _, [%0], %1;"
                 :: "r"(a), "r"(bytes) : "memory");
}

__device__ __forceinline__ void mbar_wait(uint32_t a, uint32_t parity) {
    asm volatile(
        "{\n\t"
        ".reg .pred P;\n\t"
        "W%=:\n\t"
        "mbarrier.try_wait.parity.acquire.cta.shared::cta.b64 P, [%0], %1;\n\t"
        "@P bra D%=;\n\t"
        "bra W%=;\n\t"
        "D%=:\n\t"
        "}"
        :: "r"(a), "r"(parity) : "memory");
}

__device__ __forceinline__ void tma2d(uint32_t dst, const CUtensorMap* map,
                                      int cx, int cy, uint32_t mbar) {
    asm volatile(
        "cp.async.bulk.tensor.2d.shared::cta.global.tile.mbarrier::complete_tx::bytes "
        "[%0], [%1, {%2, %3}], [%4];"
        :: "r"(dst), "l"(map), "r"(cx), "r"(cy), "r"(mbar) : "memory");
}

// ------------------------------------------------------------------
// Kernel 1: per-row |x|^2, softplus(x.cw+cb), fp16 (x*32) copy
// ------------------------------------------------------------------
__global__ __launch_bounds__(256) void k_rowstat(const float* __restrict__ x,
                                                 const float* __restrict__ cw,
                                                 const float* __restrict__ cb) {
    int row = blockIdx.x;
    const float4* xr = (const float4*)(x + (size_t)row * DIM);
    const float4* cr = (const float4*)cw;
    __half2* xo = (__half2*)(g_xh + (size_t)row * DIM);
    float dot = 0.f, nn = 0.f;
    #pragma unroll
    for (int i = 0; i < 2; i++) {
        int idx = threadIdx.x + i * 256;
        float4 a = xr[idx], b = cr[idx];
        dot += a.x * b.x + a.y * b.y + a.z * b.z + a.w * b.w;
        nn  += a.x * a.x + a.y * a.y + a.z * a.z + a.w * a.w;
        xo[idx * 2]     = __floats2half2_rn(a.x * SCALE, a.y * SCALE);
        xo[idx * 2 + 1] = __floats2half2_rn(a.z * SCALE, a.w * SCALE);
    }
    __shared__ float sbuf[8];
    dot = blockReduceSum(dot, sbuf);
    nn  = blockReduceSum(nn, sbuf);
    if (threadIdx.x == 0) {
        g_xn2[row] = nn;
        float l = dot + cb[0];
        g_sp[row] = fmaxf(l, 0.f) + log1pf(expf(-fabsf(l)));
    }
}

// ------------------------------------------------------------------
// Kernel 1b: W -> fp16 (w*32)
// ------------------------------------------------------------------
__global__ __launch_bounds__(256) void k_cvtW(const float* __restrict__ W) {
    int i = blockIdx.x * 256 + threadIdx.x;
    float4 v = ((const float4*)W)[i];
    __half2* o = (__half2*)g_wh;
    o[i * 2]     = __floats2half2_rn(v.x * SCALE, v.y * SCALE);
    o[i * 2 + 1] = __floats2half2_rn(v.z * SCALE, v.w * SCALE);
}

// ------------------------------------------------------------------
// Kernel 2: scalars
// ------------------------------------------------------------------
__global__ __launch_bounds__(256) void k_scalars(const float* __restrict__ anchors,
                                                 const float* __restrict__ aw) {
    __shared__ float sbuf[8];
    float s = 0.f;
    for (int i = threadIdx.x; i < NROWS; i += 256) s += g_sp[i];
    s = blockReduceSum(s, sbuf);
    float c = s / (float)NROWS;

    for (int k = 0; k < NK; k++) {
        float v = 0.f;
        for (int j = threadIdx.x; j < DIM; j += 256) {
            float a = anchors[k * DIM + j];
            v += a * a;
        }
        v = blockReduceSum(v, sbuf);
        if (threadIdx.x == 0) g_an2[k] = v;
    }

    if (threadIdx.x == 0) {
        g_c = c;
        g_sc = sqrtf(c);
        float m = fmaxf(fmaxf(aw[0], aw[1]), fmaxf(aw[2], aw[3]));
        float e0 = expf(aw[0] - m), e1 = expf(aw[1] - m);
        float e2 = expf(aw[2] - m), e3 = expf(aw[3] - m);
        float inv = 1.f / (e0 + e1 + e2 + e3);
        g_w[0] = e0 * inv; g_w[1] = e1 * inv;
        g_w[2] = e2 * inv; g_w[3] = e3 * inv;
    }
}

// ------------------------------------------------------------------
// Kernel 3: TMA-fed fp16 mma.sync GEMM (128x256 block, 64x32 warps, 512 thr)
// ------------------------------------------------------------------
__device__ __forceinline__ float row_scale(int r, float sc) {
    float n = fmaxf(sqrtf(g_xn2[r]), EPSF);
    float z = sc * n;
    return atanhf(clip_artanh_arg(z)) / z;
}

__global__ void __launch_bounds__(512, 1) k_gemm(
    const __grid_constant__ CUtensorMap xmap,
    const __grid_constant__ CUtensorMap wmap,
    const float* __restrict__ bias,
    const float* __restrict__ anchors)
{
    extern __shared__ char smem[];
    uint32_t sb = smem_u32(smem);
    const int tid  = threadIdx.x;
    const int lane = tid & 31;
    const int warp = tid >> 5;
    const int bm = blockIdx.y * MT;
    const int bn = blockIdx.x * NT;
    const int wm = (warp >> 3) * 64;   // 2 M-warps
    const int wn = (warp & 7) * 32;    // 8 N-warps
    const uint32_t mb = sb + SOFF_MBAR;

    float acc[4][4][4];
    #pragma unroll
    for (int mi = 0; mi < 4; mi++)
        #pragma unroll
        for (int ni = 0; ni < 4; ni++)
            #pragma unroll
            for (int q = 0; q < 4; q++) acc[mi][ni][q] = 0.f;

    const int g  = lane >> 2;
    const int tg = lane & 3;

    // ldmatrix per-lane addressing (SW128 swizzle: row*128 + (kb ^ ((row&7)<<4)))
    const uint32_t a_row = wm + (lane & 15);
    const uint32_t aq    = ((lane >> 4) * 16) ^ ((a_row & 7) << 4);
    const uint32_t b_row = wn + ((lane >> 4) << 3) + (lane & 7);
    const uint32_t bq    = (((lane >> 3) & 1) * 16) ^ ((b_row & 7) << 4);

    if (tid == 0) {
        #pragma unroll
        for (int s = 0; s < NSTAGE; s++) mbar_init(mb + 8 * s, 1);
    }
    __syncthreads();
    if (tid == 0) {
        #pragma unroll
        for (int s = 0; s < 3; s++) {
            uint32_t abase = sb + s * STAGE_BYTES;
            mbar_expect(mb + 8 * s, STAGE_BYTES);
            tma2d(abase, &xmap, s * KC, bm, mb + 8 * s);
            tma2d(abase + A_STAGE_BYTES, &wmap, s * KC, bn, mb + 8 * s);
        }
    }

    for (int i = 0; i < NITER; i++) {
        int s = i & 3;
        mbar_wait(mb + 8 * s, (i >> 2) & 1);
        // Issue prefetch for i+3 NOW: its buffer ((i+3)&3 == (i-1)&3) was
        // freed by the __syncthreads at the end of iteration i-1.
        if (tid == 0 && i + 3 < NITER) {
            int j = i + 3, s2 = j & 3;
            uint32_t ab2 = sb + s2 * STAGE_BYTES;
            mbar_expect(mb + 8 * s2, STAGE_BYTES);
            tma2d(ab2, &xmap, j * KC, bm, mb + 8 * s2);
            tma2d(ab2 + A_STAGE_BYTES, &wmap, j * KC, bn, mb + 8 * s2);
        }
        uint32_t abase = sb + s * STAGE_BYTES;
        uint32_t bbase = abase + A_STAGE_BYTES;

        #pragma unroll
        for (int ks = 0; ks < 4; ks++) {
            uint32_t a[4][4];
            #pragma unroll
            for (int mi = 0; mi < 4; mi++)
                ldsm4(abase + (a_row + mi * 16) * 128 + ((ks * 32) ^ aq),
                      a[mi][0], a[mi][1], a[mi][2], a[mi][3]);
            uint32_t b[4][2];
            #pragma unroll
            for (int p = 0; p < 2; p++)
                ldsm4(bbase + (b_row + p * 16) * 128 + ((ks * 32) ^ bq),
                      b[2 * p][0], b[2 * p][1], b[2 * p + 1][0], b[2 * p + 1][1]);
            #pragma unroll
            for (int mi = 0; mi < 4; mi++)
                #pragma unroll
                for (int ni = 0; ni < 4; ni++) {
                    asm volatile(
                        "mma.sync.aligned.m16n8k16.row.col.f32.f16.f16.f32 "
                        "{%0,%1,%2,%3}, {%4,%5,%6,%7}, {%8,%9}, {%0,%1,%2,%3};\n"
                        : "+f"(acc[mi][ni][0]), "+f"(acc[mi][ni][1]),
                          "+f"(acc[mi][ni][2]), "+f"(acc[mi][ni][3])
                        : "r"(a[mi][0]), "r"(a[mi][1]), "r"(a[mi][2]), "r"(a[mi][3]),
                          "r"(b[ni][0]), "r"(b[ni][1]));
                }
        }
        __syncthreads();   // all warps done with stage i's buffers
    }

    // Epilogue: h = s_row * acc/1024 + bias; store + per-row partial sums
    float sc = g_sc;
    float bz0[4], bz1[4];
    #pragma unroll
    for (int ni = 0; ni < 4; ni++) {
        int cc = bn + wn + ni * 8 + tg * 2;
        bz0[ni] = bias[cc];
        bz1[ni] = bias[cc + 1];
    }
    #pragma unroll
    for (int mi = 0; mi < 4; mi++) {
        int r0 = bm + wm + mi * 16 + g;
        float s0 = row_scale(r0, sc) * SCALE_INV;
        float s1 = row_scale(r0 + 8, sc) * SCALE_INV;
        float p0[5] = {0.f, 0.f, 0.f, 0.f, 0.f};
        float p1[5] = {0.f, 0.f, 0.f, 0.f, 0.f};
        #pragma unroll
        for (int ni = 0; ni < 4; ni++) {
            int cc = bn + wn + ni * 8 + tg * 2;
            float h00 = fmaf(s0, acc[mi][ni][0], bz0[ni]);
            float h01 = fmaf(s0, acc[mi][ni][1], bz1[ni]);
            float h10 = fmaf(s1, acc[mi][ni][2], bz0[ni]);
            float h11 = fmaf(s1, acc[mi][ni][3], bz1[ni]);
            float* o0 = g_h + (size_t)r0 * DIM + cc;
            o0[0] = h00; o0[1] = h01;
            float* o1 = g_h + (size_t)(r0 + 8) * DIM + cc;
            o1[0] = h10; o1[1] = h11;
            p0[0] += h00 * h00 + h01 * h01;
            p1[0] += h10 * h10 + h11 * h11;
            #pragma unroll
            for (int k = 0; k < NK; k++) {
                float a0 = anchors[k * DIM + cc];
                float a1 = anchors[k * DIM + cc + 1];
                p0[1 + k] += h00 * a0 + h01 * a1;
                p1[1 + k] += h10 * a0 + h11 * a1;
            }
        }
        #pragma unroll
        for (int q = 0; q < 5; q++) {
            p0[q] += __shfl_xor_sync(0xffffffffu, p0[q], 1);
            p0[q] += __shfl_xor_sync(0xffffffffu, p0[q], 2);
            p1[q] += __shfl_xor_sync(0xffffffffu, p1[q], 1);
            p1[q] += __shfl_xor_sync(0xffffffffu, p1[q], 2);
        }
        if (tg == 0) {
            int pi = blockIdx.x * 8 + (warp & 7);   // 8 n-blocks * 8 n-warps = 64
            float* d0 = g_part + ((size_t)r0 * NPART + pi) * 5;
            float* d1 = g_part + ((size_t)(r0 + 8) * NPART + pi) * 5;
            #pragma unroll
            for (int q = 0; q < 5; q++) { d0[q] = p0[q]; d1[q] = p1[q]; }
        }
    }
}

// ------------------------------------------------------------------
// Kernel 4: per-row coefficients + streaming combine
//   out = Ae*h + sum_k Bk*a_k
// ------------------------------------------------------------------
__global__ __launch_bounds__(256) void k_final(const float* __restrict__ anchors,
                                               const float* __restrict__ tv,
                                               float* __restrict__ out) {
    int row = blockIdx.x;
    int tid = threadIdx.x;
    int w = tid >> 5, lane = tid & 31;

    __shared__ float sred[5];
    __shared__ float scoef[5];

    // Reduce 64 partials x 5 quantities: warp q handles quantity q
    if (w < 5) {
        const float* pp = g_part + (size_t)row * NPART * 5;
        float v = pp[lane * 5 + w] + pp[(lane + 32) * 5 + w];
        #pragma unroll
        for (int o = 16; o > 0; o >>= 1) v += __shfl_xor_sync(0xffffffffu, v, o);
        if (lane == 0) sred[w] = v;
    }
    __syncthreads();

    if (tid == 0) {
        float c = g_c, sc = g_sc;
        float h2 = sred[0];
        float m = fmaxf(sqrtf(h2), EPSF);
        float scm = sc * m;
        float e = tanhf(scm) / scm;
        float y2 = e * e * h2;
        float Acoef = 0.f;
        #pragma unroll
        for (int k = 0; k < NK; k++) {
            float ya  = e * sred[1 + k];
            float an2 = g_an2[k];
            float P  = 1.f - 2.f * c * ya + c * an2;
            float Q  = 1.f - c * y2;
            float D1 = fmaxf(1.f - 2.f * c * ya + c * c * y2 * an2, EPSF);
            float diff2 = (P * P * y2 - 2.f * P * Q * ya + Q * Q * an2) / (D1 * D1);
            float nd = fmaxf(sqrtf(fmaxf(diff2, 0.f)), EPSF);
            float z  = sc * nd;
            float ar = atanhf(clip_artanh_arg(z));
            float tau = tanhf(tv[k] * ar) / z;
            float uy = -tau * P / D1;
            float ua =  tau * Q / D1;
            float xys = uy * y2 + ua * ya;
            float y2s = tau * tau * diff2;
            float den2 = fmaxf(1.f + 2.f * c * xys + c * c * y2 * y2s, EPSF);
            float alpha = (1.f + 2.f * c * xys + c * y2s + (1.f - c * y2) * uy) / den2;
            float beta  = (1.f - c * y2) * ua / den2;
            float w2 = g_w[k];
            Acoef += w2 * alpha;
            scoef[1 + k] = w2 * beta;
        }
        scoef[0] = Acoef * e;
    }
    __syncthreads();

    float Ae = scoef[0];
    float B0 = scoef[1], B1 = scoef[2], B2 = scoef[3], B3 = scoef[4];
    const float4* hr = (const float4*)(g_h + (size_t)row * DIM);
    const float4* a0 = (const float4*)(anchors);
    const float4* a1 = (const float4*)(anchors + DIM);
    const float4* a2 = (const float4*)(anchors + 2 * DIM);
    const float4* a3 = (const float4*)(anchors + 3 * DIM);
    float4* outr = (float4*)(out + (size_t)row * DIM);
    #pragma unroll
    for (int i = 0; i < 2; i++) {
        int idx = tid + i * 256;
        float4 h = hr[idx];
        float4 v0 = a0[idx], v1 = a1[idx], v2 = a2[idx], v3 = a3[idx];
        float4 o;
        o.x = Ae * h.x; o.y = Ae * h.y; o.z = Ae * h.z; o.w = Ae * h.w;
        o.x = fmaf(B0, v0.x, o.x); o.y = fmaf(B0, v0.y, o.y);
        o.z = fmaf(B0, v0.z, o.z); o.w = fmaf(B0, v0.w, o.w);
        o.x = fmaf(B1, v1.x, o.x); o.y = fmaf(B1, v1.y, o.y);
        o.z = fmaf(B1, v1.z, o.z); o.w = fmaf(B1, v1.w, o.w);
        o.x = fmaf(B2, v2.x, o.x); o.y = fmaf(B2, v2.y, o.y);
        o.z = fmaf(B2, v2.z, o.z); o.w = fmaf(B2, v2.w, o.w);
        o.x = fmaf(B3, v3.x, o.x); o.y = fmaf(B3, v3.y, o.y);
        o.z = fmaf(B3, v3.z, o.z); o.w = fmaf(B3, v3.w, o.w);
        outr[idx] = o;
    }
}

// ------------------------------------------------------------------
// Launch
// ------------------------------------------------------------------
typedef CUresult (*tmapEncodeFn)(
    CUtensorMap*, CUtensorMapDataType, cuuint32_t, void*,
    const cuuint64_t*, const cuuint64_t*, const cuuint32_t*, const cuuint32_t*,
    CUtensorMapInterleave, CUtensorMapSwizzle, CUtensorMapL2promotion,
    CUtensorMapFloatOOBfill);

extern "C" void kernel_launch(void* const* d_in, const int* in_sizes, int n_in,
                              void* d_out, int out_size) {
    const float* x       = (const float*)d_in[0];
    const float* weight  = (const float*)d_in[1];
    const float* bias    = (const float*)d_in[2];
    const float* cw      = (const float*)d_in[3];
    const float* cb      = (const float*)d_in[4];
    const float* anchors = (const float*)d_in[5];
    const float* tv      = (const float*)d_in[6];
    const float* aw      = (const float*)d_in[7];
    float* out = (float*)d_out;

    cudaFuncSetAttribute(k_gemm, cudaFuncAttributeMaxDynamicSharedMemorySize,
                         SMEM_TOTAL);

    // Build tensor maps for the fp16 scratch tensors
    void* xptr = nullptr;
    void* wptr = nullptr;
    cudaGetSymbolAddress(&xptr, g_xh);
    cudaGetSymbolAddress(&wptr, g_wh);

    tmapEncodeFn encode = nullptr;
    cudaDriverEntryPointQueryResult qr;
    cudaGetDriverEntryPointByVersion("cuTensorMapEncodeTiled", (void**)&encode,
                                     12000, cudaEnableDefault, &qr);

    CUtensorMap xmap, wmap;
    {
        cuuint64_t gdim[2] = {DIM, NROWS};
        cuuint64_t gstr[1] = {DIM * 2};           // bytes between rows
        cuuint32_t box[2]  = {KC, MT};            // 64 halves x 128 rows
        cuuint32_t est[2]  = {1, 1};
        encode(&xmap, CU_TENSOR_MAP_DATA_TYPE_UINT16, 2, xptr,
               gdim, gstr, box, est,
               CU_TENSOR_MAP_INTERLEAVE_NONE, CU_TENSOR_MAP_SWIZZLE_128B,
               CU_TENSOR_MAP_L2_PROMOTION_L2_128B,
               CU_TENSOR_MAP_FLOAT_OOB_FILL_NONE);
    }
    {
        cuuint64_t gdim[2] = {DIM, DIM};
        cuuint64_t gstr[1] = {DIM * 2};
        cuuint32_t box[2]  = {KC, NT};            // 64 halves x 256 rows
        cuuint32_t est[2]  = {1, 1};
        encode(&wmap, CU_TENSOR_MAP_DATA_TYPE_UINT16, 2, wptr,
               gdim, gstr, box, est,
               CU_TENSOR_MAP_INTERLEAVE_NONE, CU_TENSOR_MAP_SWIZZLE_128B,
               CU_TENSOR_MAP_L2_PROMOTION_L2_128B,
               CU_TENSOR_MAP_FLOAT_OOB_FILL_NONE);
    }

    k_rowstat<<<NROWS, 256>>>(x, cw, cb);
    k_cvtW<<<DIM * DIM / 4 / 256, 256>>>(weight);
    k_scalars<<<1, 256>>>(anchors, aw);
    dim3 grid(DIM / NT, NROWS / MT);       // 8 x 32 = 256 CTAs
    k_gemm<<<grid, 512, SMEM_TOTAL>>>(xmap, wmap, bias, anchors);
    k_final<<<NROWS, 256>>>(anchors, tv, out);
}

// round 11
// speedup vs baseline: 2.4740x; 1.0962x over previous
#include <cuda_runtime.h>
#include <cuda_fp16.h>
#include <cuda.h>
#include <cstdint>
#include <math.h>

#define NROWS 4096
#define DIM   2048
#define NK    4
#define EPSF  1e-6f

// GEMM tiling (fp16, mma.m16n8k16), block 128x256, warp 64x64, 8 warps
#define MT 128
#define NT 256
#define KC 64                     // K halves per stage (128B rows -> SW128)
#define NSTAGE 4
#define NITER (DIM / KC)          // 32
#define A_STAGE_BYTES (MT * 128)               // 16384
#define B_STAGE_BYTES (NT * 128)               // 32768
#define STAGE_BYTES   (A_STAGE_BYTES + B_STAGE_BYTES)   // 49152
#define SOFF_FULL     (NSTAGE * STAGE_BYTES)   // 196608
#define SOFF_EMPTY    (SOFF_FULL + NSTAGE * 8)
#define SMEM_TOTAL    (SOFF_EMPTY + NSTAGE * 8 + 32)

#define NPART 32                  // per-row partial slots (8 n-blocks * 4 n-warps)

#define SCALE     32.0f
#define SCALE_INV 9.765625e-4f    // 1/1024

// ------------------------------------------------------------------
// Device scratch
// ------------------------------------------------------------------
__device__ float  g_h[(size_t)NROWS * DIM];
__device__ __half g_xh[(size_t)NROWS * DIM];
__device__ __half g_wh[(size_t)DIM * DIM];
__device__ float  g_part[(size_t)NROWS * NPART * 5];
__device__ float  g_xn2[NROWS];
__device__ float  g_sp[NROWS];
__device__ float  g_c;
__device__ float  g_sc;
__device__ float  g_an2[NK];
__device__ float  g_w[NK];

// ------------------------------------------------------------------
// Helpers
// ------------------------------------------------------------------
__device__ __forceinline__ uint32_t smem_u32(const void* p) {
    uint32_t a;
    asm("{ .reg .u64 t; cvta.to.shared.u64 t, %1; cvt.u32.u64 %0, t; }"
        : "=r"(a) : "l"(p));
    return a;
}

__device__ __forceinline__ float blockReduceSum(float v, float* sbuf) {
    #pragma unroll
    for (int o = 16; o > 0; o >>= 1) v += __shfl_xor_sync(0xffffffffu, v, o);
    int w = threadIdx.x >> 5;
    if ((threadIdx.x & 31) == 0) sbuf[w] = v;
    __syncthreads();
    if (threadIdx.x < 32) {
        float t = (threadIdx.x < 8) ? sbuf[threadIdx.x] : 0.f;
        #pragma unroll
        for (int o = 4; o > 0; o >>= 1) t += __shfl_xor_sync(0xffffffffu, t, o);
        if (threadIdx.x == 0) sbuf[0] = t;
    }
    __syncthreads();
    float r = sbuf[0];
    __syncthreads();
    return r;
}

__device__ __forceinline__ float clip_artanh_arg(float z) {
    return fminf(fmaxf(z, -1.f + 1e-5f), 1.f - 1e-5f);
}

__device__ __forceinline__ void ldsm4(uint32_t addr, uint32_t& r0, uint32_t& r1,
                                      uint32_t& r2, uint32_t& r3) {
    asm volatile("ldmatrix.sync.aligned.m8n8.x4.shared.b16 {%0,%1,%2,%3}, [%4];"
                 : "=r"(r0), "=r"(r1), "=r"(r2), "=r"(r3) : "r"(addr));
}

__device__ __forceinline__ void mbar_init(uint32_t a, uint32_t cnt) {
    asm volatile("mbarrier.init.shared.b64 [%0], %1;" :: "r"(a), "r"(cnt) : "memory");
}

__device__ __forceinline__ void mbar_expect(uint32_t a, uint32_t bytes) {
    asm volatile("mbarrier.arrive.expect_tx.shared.b64 _, [%0], %1;"
                 :: "r"(a), "r"(bytes) : "memory");
}

__device__ __forceinline__ void mbar_arrive(uint32_t a) {
    asm volatile("mbarrier.arrive.release.cta.shared.b64 _, [%0];"
                 :: "r"(a) : "memory");
}

__device__ __forceinline__ void mbar_wait(uint32_t a, uint32_t parity) {
    asm volatile(
        "{\n\t"
        ".reg .pred P;\n\t"
        "W%=:\n\t"
        "mbarrier.try_wait.parity.acquire.cta.shared::cta.b64 P, [%0], %1;\n\t"
        "@P bra D%=;\n\t"
        "bra W%=;\n\t"
        "D%=:\n\t"
        "}"
        :: "r"(a), "r"(parity) : "memory");
}

__device__ __forceinline__ void tma2d(uint32_t dst, const CUtensorMap* map,
                                      int cx, int cy, uint32_t mbar) {
    asm volatile(
        "cp.async.bulk.tensor.2d.shared::cta.global.tile.mbarrier::complete_tx::bytes "
        "[%0], [%1, {%2, %3}], [%4];"
        :: "r"(dst), "l"(map), "r"(cx), "r"(cy), "r"(mbar) : "memory");
}

// ------------------------------------------------------------------
// Kernel 1: per-row |x|^2, softplus(x.cw+cb), fp16 (x*32) copy
// ------------------------------------------------------------------
__global__ __launch_bounds__(256) void k_rowstat(const float* __restrict__ x,
                                                 const float* __restrict__ cw,
                                                 const float* __restrict__ cb) {
    int row = blockIdx.x;
    const float4* xr = (const float4*)(x + (size_t)row * DIM);
    const float4* cr = (const float4*)cw;
    __half2* xo = (__half2*)(g_xh + (size_t)row * DIM);
    float dot = 0.f, nn = 0.f;
    #pragma unroll
    for (int i = 0; i < 2; i++) {
        int idx = threadIdx.x + i * 256;
        float4 a = xr[idx], b = cr[idx];
        dot += a.x * b.x + a.y * b.y + a.z * b.z + a.w * b.w;
        nn  += a.x * a.x + a.y * a.y + a.z * a.z + a.w * a.w;
        xo[idx * 2]     = __floats2half2_rn(a.x * SCALE, a.y * SCALE);
        xo[idx * 2 + 1] = __floats2half2_rn(a.z * SCALE, a.w * SCALE);
    }
    __shared__ float sbuf[8];
    dot = blockReduceSum(dot, sbuf);
    nn  = blockReduceSum(nn, sbuf);
    if (threadIdx.x == 0) {
        g_xn2[row] = nn;
        float l = dot + cb[0];
        g_sp[row] = fmaxf(l, 0.f) + log1pf(expf(-fabsf(l)));
    }
}

// ------------------------------------------------------------------
// Kernel 1b: W -> fp16 (w*32)
// ------------------------------------------------------------------
__global__ __launch_bounds__(256) void k_cvtW(const float* __restrict__ W) {
    int i = blockIdx.x * 256 + threadIdx.x;
    float4 v = ((const float4*)W)[i];
    __half2* o = (__half2*)g_wh;
    o[i * 2]     = __floats2half2_rn(v.x * SCALE, v.y * SCALE);
    o[i * 2 + 1] = __floats2half2_rn(v.z * SCALE, v.w * SCALE);
}

// ------------------------------------------------------------------
// Kernel 2: scalars
// ------------------------------------------------------------------
__global__ __launch_bounds__(256) void k_scalars(const float* __restrict__ anchors,
                                                 const float* __restrict__ aw) {
    __shared__ float sbuf[8];
    float s = 0.f;
    for (int i = threadIdx.x; i < NROWS; i += 256) s += g_sp[i];
    s = blockReduceSum(s, sbuf);
    float c = s / (float)NROWS;

    for (int k = 0; k < NK; k++) {
        float v = 0.f;
        for (int j = threadIdx.x; j < DIM; j += 256) {
            float a = anchors[k * DIM + j];
            v += a * a;
        }
        v = blockReduceSum(v, sbuf);
        if (threadIdx.x == 0) g_an2[k] = v;
    }

    if (threadIdx.x == 0) {
        g_c = c;
        g_sc = sqrtf(c);
        float m = fmaxf(fmaxf(aw[0], aw[1]), fmaxf(aw[2], aw[3]));
        float e0 = expf(aw[0] - m), e1 = expf(aw[1] - m);
        float e2 = expf(aw[2] - m), e3 = expf(aw[3] - m);
        float inv = 1.f / (e0 + e1 + e2 + e3);
        g_w[0] = e0 * inv; g_w[1] = e1 * inv;
        g_w[2] = e2 * inv; g_w[3] = e3 * inv;
    }
}

// ------------------------------------------------------------------
// Kernel 3: TMA-fed fp16 mma.sync GEMM, mbarrier-only mainloop
// ------------------------------------------------------------------
__device__ __forceinline__ float row_scale(int r, float sc) {
    float n = fmaxf(sqrtf(g_xn2[r]), EPSF);
    float z = sc * n;
    return atanhf(clip_artanh_arg(z)) / z;
}

__global__ void __launch_bounds__(256, 1) k_gemm(
    const __grid_constant__ CUtensorMap xmap,
    const __grid_constant__ CUtensorMap wmap,
    const float* __restrict__ bias,
    const float* __restrict__ anchors)
{
    extern __shared__ char smem[];
    uint32_t sb = smem_u32(smem);
    const int tid  = threadIdx.x;
    const int lane = tid & 31;
    const int warp = tid >> 5;
    const int bm = blockIdx.y * MT;
    const int bn = blockIdx.x * NT;
    const int wm = (warp >> 2) * 64;   // 2 M-warps
    const int wn = (warp & 3) * 64;    // 4 N-warps
    const uint32_t mbF = sb + SOFF_FULL;
    const uint32_t mbE = sb + SOFF_EMPTY;

    float acc[4][8][4];
    #pragma unroll
    for (int mi = 0; mi < 4; mi++)
        #pragma unroll
        for (int ni = 0; ni < 8; ni++)
            #pragma unroll
            for (int q = 0; q < 4; q++) acc[mi][ni][q] = 0.f;

    const int g  = lane >> 2;
    const int tg = lane & 3;

    // ldmatrix per-lane addressing (SW128 swizzle: row*128 + (kb ^ ((row&7)<<4)))
    const uint32_t a_row = wm + (lane & 15);
    const uint32_t aq    = ((lane >> 4) * 16) ^ ((a_row & 7) << 4);
    const uint32_t b_row = wn + ((lane >> 4) << 3) + (lane & 7);
    const uint32_t bq    = (((lane >> 3) & 1) * 16) ^ ((b_row & 7) << 4);

    if (tid == 0) {
        #pragma unroll
        for (int s = 0; s < NSTAGE; s++) {
            mbar_init(mbF + 8 * s, 1);
            mbar_init(mbE + 8 * s, 8);   // one arrive per warp
        }
    }
    __syncthreads();
    if (tid == 0) {
        #pragma unroll
        for (int s = 0; s < 3; s++) {
            uint32_t abase = sb + s * STAGE_BYTES;
            mbar_expect(mbF + 8 * s, STAGE_BYTES);
            tma2d(abase, &xmap, s * KC, bm, mbF + 8 * s);
            tma2d(abase + A_STAGE_BYTES, &wmap, s * KC, bn, mbF + 8 * s);
        }
    }

    for (int i = 0; i < NITER; i++) {
        int s = i & 3;
        mbar_wait(mbF + 8 * s, (i >> 2) & 1);
        uint32_t abase = sb + s * STAGE_BYTES;
        uint32_t bbase = abase + A_STAGE_BYTES;

        #pragma unroll
        for (int ks = 0; ks < 4; ks++) {
            uint32_t a[4][4];
            #pragma unroll
            for (int mi = 0; mi < 4; mi++)
                ldsm4(abase + (a_row + mi * 16) * 128 + ((ks * 32) ^ aq),
                      a[mi][0], a[mi][1], a[mi][2], a[mi][3]);
            uint32_t b[8][2];
            #pragma unroll
            for (int p = 0; p < 4; p++)
                ldsm4(bbase + (b_row + p * 16) * 128 + ((ks * 32) ^ bq),
                      b[2 * p][0], b[2 * p][1], b[2 * p + 1][0], b[2 * p + 1][1]);
            #pragma unroll
            for (int mi = 0; mi < 4; mi++)
                #pragma unroll
                for (int ni = 0; ni < 8; ni++) {
                    asm volatile(
                        "mma.sync.aligned.m16n8k16.row.col.f32.f16.f16.f32 "
                        "{%0,%1,%2,%3}, {%4,%5,%6,%7}, {%8,%9}, {%0,%1,%2,%3};\n"
                        : "+f"(acc[mi][ni][0]), "+f"(acc[mi][ni][1]),
                          "+f"(acc[mi][ni][2]), "+f"(acc[mi][ni][3])
                        : "r"(a[mi][0]), "r"(a[mi][1]), "r"(a[mi][2]), "r"(a[mi][3]),
                          "r"(b[ni][0]), "r"(b[ni][1]));
                }
        }
        // Fragments for stage s fully consumed by this warp -> release buffer.
        if (lane == 0) mbar_arrive(mbE + 8 * s);

        // Producer: refill stage (i+3)&3 once all warps released it (iter i-1).
        if (tid == 0 && i + 3 < NITER) {
            int j = i + 3, s2 = j & 3, f = j >> 2;
            if (f >= 1) mbar_wait(mbE + 8 * s2, (f - 1) & 1);
            uint32_t ab2 = sb + s2 * STAGE_BYTES;
            mbar_expect(mbF + 8 * s2, STAGE_BYTES);
            tma2d(ab2, &xmap, j * KC, bm, mbF + 8 * s2);
            tma2d(ab2 + A_STAGE_BYTES, &wmap, j * KC, bn, mbF + 8 * s2);
        }
    }

    // Epilogue: h = s_row * acc/1024 + bias; store + per-row partial sums
    float sc = g_sc;
    float bz0[8], bz1[8];
    #pragma unroll
    for (int ni = 0; ni < 8; ni++) {
        int cc = bn + wn + ni * 8 + tg * 2;
        bz0[ni] = bias[cc];
        bz1[ni] = bias[cc + 1];
    }
    #pragma unroll
    for (int mi = 0; mi < 4; mi++) {
        int r0 = bm + wm + mi * 16 + g;
        float s0 = row_scale(r0, sc) * SCALE_INV;
        float s1 = row_scale(r0 + 8, sc) * SCALE_INV;
        float p0[5] = {0.f, 0.f, 0.f, 0.f, 0.f};
        float p1[5] = {0.f, 0.f, 0.f, 0.f, 0.f};
        #pragma unroll
        for (int ni = 0; ni < 8; ni++) {
            int cc = bn + wn + ni * 8 + tg * 2;
            float h00 = fmaf(s0, acc[mi][ni][0], bz0[ni]);
            float h01 = fmaf(s0, acc[mi][ni][1], bz1[ni]);
            float h10 = fmaf(s1, acc[mi][ni][2], bz0[ni]);
            float h11 = fmaf(s1, acc[mi][ni][3], bz1[ni]);
            float* o0 = g_h + (size_t)r0 * DIM + cc;
            o0[0] = h00; o0[1] = h01;
            float* o1 = g_h + (size_t)(r0 + 8) * DIM + cc;
            o1[0] = h10; o1[1] = h11;
            p0[0] += h00 * h00 + h01 * h01;
            p1[0] += h10 * h10 + h11 * h11;
            #pragma unroll
            for (int k = 0; k < NK; k++) {
                float a0 = anchors[k * DIM + cc];
                float a1 = anchors[k * DIM + cc + 1];
                p0[1 + k] += h00 * a0 + h01 * a1;
                p1[1 + k] += h10 * a0 + h11 * a1;
            }
        }
        #pragma unroll
        for (int q = 0; q < 5; q++) {
            p0[q] += __shfl_xor_sync(0xffffffffu, p0[q], 1);
            p0[q] += __shfl_xor_sync(0xffffffffu, p0[q], 2);
            p1[q] += __shfl_xor_sync(0xffffffffu, p1[q], 1);
            p1[q] += __shfl_xor_sync(0xffffffffu, p1[q], 2);
        }
        if (tg == 0) {
            int pi = blockIdx.x * 4 + (warp & 3);   // 8 n-blocks * 4 n-warps = 32
            float* d0 = g_part + ((size_t)r0 * NPART + pi) * 5;
            float* d1 = g_part + ((size_t)(r0 + 8) * NPART + pi) * 5;
            #pragma unroll
            for (int q = 0; q < 5; q++) { d0[q] = p0[q]; d1[q] = p1[q]; }
        }
    }
}

// ------------------------------------------------------------------
// Kernel 4: per-row coefficients + streaming combine
// ------------------------------------------------------------------
__global__ __launch_bounds__(256) void k_final(const float* __restrict__ anchors,
                                               const float* __restrict__ tv,
                                               float* __restrict__ out) {
    int row = blockIdx.x;
    int tid = threadIdx.x;
    int w = tid >> 5, lane = tid & 31;

    __shared__ float sred[5];
    __shared__ float scoef[5];

    // Reduce 32 partials x 5 quantities: warp q handles quantity q
    if (w < 5) {
        const float* pp = g_part + (size_t)row * NPART * 5;
        float v = pp[lane * 5 + w];
        #pragma unroll
        for (int o = 16; o > 0; o >>= 1) v += __shfl_xor_sync(0xffffffffu, v, o);
        if (lane == 0) sred[w] = v;
    }
    __syncthreads();

    if (tid == 0) {
        float c = g_c, sc = g_sc;
        float h2 = sred[0];
        float m = fmaxf(sqrtf(h2), EPSF);
        float scm = sc * m;
        float e = tanhf(scm) / scm;
        float y2 = e * e * h2;
        float Acoef = 0.f;
        #pragma unroll
        for (int k = 0; k < NK; k++) {
            float ya  = e * sred[1 + k];
            float an2 = g_an2[k];
            float P  = 1.f - 2.f * c * ya + c * an2;
            float Q  = 1.f - c * y2;
            float D1 = fmaxf(1.f - 2.f * c * ya + c * c * y2 * an2, EPSF);
            float diff2 = (P * P * y2 - 2.f * P * Q * ya + Q * Q * an2) / (D1 * D1);
            float nd = fmaxf(sqrtf(fmaxf(diff2, 0.f)), EPSF);
            float z  = sc * nd;
            float ar = atanhf(clip_artanh_arg(z));
            float tau = tanhf(tv[k] * ar) / z;
            float uy = -tau * P / D1;
            float ua =  tau * Q / D1;
            float xys = uy * y2 + ua * ya;
            float y2s = tau * tau * diff2;
            float den2 = fmaxf(1.f + 2.f * c * xys + c * c * y2 * y2s, EPSF);
            float alpha = (1.f + 2.f * c * xys + c * y2s + (1.f - c * y2) * uy) / den2;
            float beta  = (1.f - c * y2) * ua / den2;
            float w2 = g_w[k];
            Acoef += w2 * alpha;
            scoef[1 + k] = w2 * beta;
        }
        scoef[0] = Acoef * e;
    }
    __syncthreads();

    float Ae = scoef[0];
    float B0 = scoef[1], B1 = scoef[2], B2 = scoef[3], B3 = scoef[4];
    const float4* hr = (const float4*)(g_h + (size_t)row * DIM);
    const float4* a0 = (const float4*)(anchors);
    const float4* a1 = (const float4*)(anchors + DIM);
    const float4* a2 = (const float4*)(anchors + 2 * DIM);
    const float4* a3 = (const float4*)(anchors + 3 * DIM);
    float4* outr = (float4*)(out + (size_t)row * DIM);
    #pragma unroll
    for (int i = 0; i < 2; i++) {
        int idx = tid + i * 256;
        float4 h = hr[idx];
        float4 v0 = a0[idx], v1 = a1[idx], v2 = a2[idx], v3 = a3[idx];
        float4 o;
        o.x = Ae * h.x; o.y = Ae * h.y; o.z = Ae * h.z; o.w = Ae * h.w;
        o.x = fmaf(B0, v0.x, o.x); o.y = fmaf(B0, v0.y, o.y);
        o.z = fmaf(B0, v0.z, o.z); o.w = fmaf(B0, v0.w, o.w);
        o.x = fmaf(B1, v1.x, o.x); o.y = fmaf(B1, v1.y, o.y);
        o.z = fmaf(B1, v1.z, o.z); o.w = fmaf(B1, v1.w, o.w);
        o.x = fmaf(B2, v2.x, o.x); o.y = fmaf(B2, v2.y, o.y);
        o.z = fmaf(B2, v2.z, o.z); o.w = fmaf(B2, v2.w, o.w);
        o.x = fmaf(B3, v3.x, o.x); o.y = fmaf(B3, v3.y, o.y);
        o.z = fmaf(B3, v3.z, o.z); o.w = fmaf(B3, v3.w, o.w);
        outr[idx] = o;
    }
}

// ------------------------------------------------------------------
// Launch
// ------------------------------------------------------------------
typedef CUresult (*tmapEncodeFn)(
    CUtensorMap*, CUtensorMapDataType, cuuint32_t, void*,
    const cuuint64_t*, const cuuint64_t*, const cuuint32_t*, const cuuint32_t*,
    CUtensorMapInterleave, CUtensorMapSwizzle, CUtensorMapL2promotion,
    CUtensorMapFloatOOBfill);

extern "C" void kernel_launch(void* const* d_in, const int* in_sizes, int n_in,
                              void* d_out, int out_size) {
    const float* x       = (const float*)d_in[0];
    const float* weight  = (const float*)d_in[1];
    const float* bias    = (const float*)d_in[2];
    const float* cw      = (const float*)d_in[3];
    const float* cb      = (const float*)d_in[4];
    const float* anchors = (const float*)d_in[5];
    const float* tv      = (const float*)d_in[6];
    const float* aw      = (const float*)d_in[7];
    float* out = (float*)d_out;

    cudaFuncSetAttribute(k_gemm, cudaFuncAttributeMaxDynamicSharedMemorySize,
                         SMEM_TOTAL);

    // Build tensor maps for the fp16 scratch tensors
    void* xptr = nullptr;
    void* wptr = nullptr;
    cudaGetSymbolAddress(&xptr, g_xh);
    cudaGetSymbolAddress(&wptr, g_wh);

    tmapEncodeFn encode = nullptr;
    cudaDriverEntryPointQueryResult qr;
    cudaGetDriverEntryPointByVersion("cuTensorMapEncodeTiled", (void**)&encode,
                                     12000, cudaEnableDefault, &qr);

    CUtensorMap xmap, wmap;
    {
        cuuint64_t gdim[2] = {DIM, NROWS};
        cuuint64_t gstr[1] = {DIM * 2};           // bytes between rows
        cuuint32_t box[2]  = {KC, MT};            // 64 halves x 128 rows
        cuuint32_t est[2]  = {1, 1};
        encode(&xmap, CU_TENSOR_MAP_DATA_TYPE_UINT16, 2, xptr,
               gdim, gstr, box, est,
               CU_TENSOR_MAP_INTERLEAVE_NONE, CU_TENSOR_MAP_SWIZZLE_128B,
               CU_TENSOR_MAP_L2_PROMOTION_L2_128B,
               CU_TENSOR_MAP_FLOAT_OOB_FILL_NONE);
    }
    {
        cuuint64_t gdim[2] = {DIM, DIM};
        cuuint64_t gstr[1] = {DIM * 2};
        cuuint32_t box[2]  = {KC, NT};            // 64 halves x 256 rows
        cuuint32_t est[2]  = {1, 1};
        encode(&wmap, CU_TENSOR_MAP_DATA_TYPE_UINT16, 2, wptr,
               gdim, gstr, box, est,
               CU_TENSOR_MAP_INTERLEAVE_NONE, CU_TENSOR_MAP_SWIZZLE_128B,
               CU_TENSOR_MAP_L2_PROMOTION_L2_128B,
               CU_TENSOR_MAP_FLOAT_OOB_FILL_NONE);
    }

    k_rowstat<<<NROWS, 256>>>(x, cw, cb);
    k_cvtW<<<DIM * DIM / 4 / 256, 256>>>(weight);
    k_scalars<<<1, 256>>>(anchors, aw);
    dim3 grid(DIM / NT, NROWS / MT);       // 8 x 32 = 256 CTAs
    k_gemm<<<grid, 256, SMEM_TOTAL>>>(xmap, wmap, bias, anchors);
    k_final<<<NROWS, 256>>>(anchors, tv, out);
}